// round 1
// baseline (speedup 1.0000x reference)
#include <cuda_runtime.h>

// ---------------------------------------------------------------------------
// GSOrthogonal: y = butterfly(x, cayley(R), cayley(L))
//   x: (16384, 4096) f32, L/R: (64, 64, 64) f32, out: (16384, 4096) f32
//
// Round-1 baseline: exact fp32, FFMA compute.
//   K1 cayley: Q = (I+S)(I-S)^{-1} per 64x64 block via no-pivot Gauss-Jordan.
//   K2 stage1: t[b][l][r] = sum_p Rq[r][l][p] * x[b][r*64+p]
//              (smem staging over 8 r's -> 32B-sector coalesced global writes)
//   K3 stage2: y[b][s*64+l] = sum_r Lq[l][s][r] * t[b][l][r]
//              (smem staging over 8 l's -> 32B-sector coalesced output writes)
// ---------------------------------------------------------------------------

#define TB 64      // batch rows per CTA tile
#define PAD 65     // smem row pad (conflict-free)

__device__ float g_Lq[64 * 64 * 64];
__device__ float g_Rq[64 * 64 * 64];
__device__ float g_t[(long)16384 * 4096];   // intermediate, [b][l][r] layout

// ---------------- Cayley: Q = (I+S)(I-S)^{-1},  S = 0.5(A - A^T) ------------
// Solve (I+S) Y = (I-S); Y = Q^T. Gauss-Jordan, no pivoting (I+S has
// positive-definite symmetric part -> pivot-free elimination is stable).
__global__ __launch_bounds__(256) void cayley_kernel(
    const float* __restrict__ Lin, const float* __restrict__ Rin) {
    __shared__ float aug[64][129];
    const int blk = blockIdx.x;                 // 0..63 -> L, 64..127 -> R
    const float* A = blk < 64 ? Lin + blk * 4096 : Rin + (blk - 64) * 4096;
    float* Q = blk < 64 ? g_Lq + blk * 4096 : g_Rq + (blk - 64) * 4096;
    const int tid = threadIdx.x;

    for (int e = tid; e < 4096; e += 256) {
        int i = e >> 6, j = e & 63;
        float s = 0.5f * (A[i * 64 + j] - A[j * 64 + i]);
        float d = (i == j) ? 1.0f : 0.0f;
        aug[i][j] = d + s;           // C   = I + S
        aug[i][64 + j] = d - s;      // RHS = I - S
    }
    __syncthreads();

    const int r  = tid >> 2;         // each row handled by 4 threads
    const int c0 = (tid & 3) * 32;   // 32-column chunk
    for (int col = 0; col < 64; col++) {
        float fac = aug[r][col] / aug[col][col];  // read before writes
        __syncthreads();
        if (r != col) {
            #pragma unroll 8
            for (int j = 0; j < 32; j++)
                aug[r][c0 + j] -= fac * aug[col][c0 + j];
        }
        __syncthreads();
    }
    // diagonal not normalized: Y[i][j] = aug[i][64+j] / aug[i][i]; Q = Y^T
    for (int e = tid; e < 4096; e += 256) {
        int a = e >> 6, b = e & 63;
        Q[a * 64 + b] = aug[b][64 + a] / aug[b][b];
    }
}

// ---------------- Stage 1: per r-block 64x64 GEMM ---------------------------
// CTA = (r-group of 8, batch tile of 64). For each r in group:
//   out[b][l] = sum_p x[b][r*64+p] * Rq[r][l][p]
// staged in smem as ts[rr][b][l], then written to g_t[b][l][r] as 8-float
// (32 B = one L2 sector) granules -> fully coalesced despite transpose.
__global__ __launch_bounds__(256) void stage1_kernel(const float* __restrict__ x) {
    extern __shared__ float sm[];
    float* xs = sm;                       // [64][PAD]
    float* ws = sm + 64 * PAD;            // [64][PAD]
    float* ts = sm + 2 * 64 * PAD;        // [8][64][64]
    const int tid = threadIdx.x;
    const int rg = blockIdx.x;            // 0..7
    const long b0 = (long)blockIdx.y * TB;
    const int ty = tid >> 4, tx = tid & 15;

    for (int rr = 0; rr < 8; rr++) {
        const int rblk = rg * 8 + rr;
        for (int e = tid; e < 4096; e += 256) {
            int b = e >> 6, p = e & 63;
            xs[b * PAD + p] = x[(b0 + b) * 4096 + rblk * 64 + p];
            ws[b * PAD + p] = g_Rq[rblk * 4096 + e];   // ws[l][p]
        }
        __syncthreads();

        float acc[4][4] = {};
        #pragma unroll 4
        for (int p = 0; p < 64; p++) {
            float xv[4], wv[4];
            #pragma unroll
            for (int i = 0; i < 4; i++) xv[i] = xs[(ty * 4 + i) * PAD + p];
            #pragma unroll
            for (int j = 0; j < 4; j++) wv[j] = ws[(tx * 4 + j) * PAD + p];
            #pragma unroll
            for (int i = 0; i < 4; i++)
                #pragma unroll
                for (int j = 0; j < 4; j++) acc[i][j] += xv[i] * wv[j];
        }
        #pragma unroll
        for (int i = 0; i < 4; i++)
            #pragma unroll
            for (int j = 0; j < 4; j++)
                ts[rr * 4096 + (ty * 4 + i) * 64 + (tx * 4 + j)] = acc[i][j];
        __syncthreads();
    }

    // transpose-write: t[b][l][rg*8 .. rg*8+7], two aligned float4 per (b,l)
    for (int e = tid; e < 4096; e += 256) {
        int b = e >> 6, l = e & 63;
        float v[8];
        #pragma unroll
        for (int k = 0; k < 8; k++) v[k] = ts[k * 4096 + e];
        float* dst = &g_t[(b0 + b) * 4096 + l * 64 + rg * 8];
        *(float4*)dst       = make_float4(v[0], v[1], v[2], v[3]);
        *(float4*)(dst + 4) = make_float4(v[4], v[5], v[6], v[7]);
    }
}

// ---------------- Stage 2: per l 64x64 GEMM + output permute ----------------
// CTA = (l-group of 8, batch tile of 64). For each l in group:
//   o[b][s] = sum_r t[b][l][r] * Lq[l][s][r]   (t rows contiguous!)
// staged os[ll][b][s], then y[b][s*64 + lg*8 + k] written as 32 B granules.
__global__ __launch_bounds__(256) void stage2_kernel(float* __restrict__ y) {
    extern __shared__ float sm[];
    float* ts = sm;                       // [64][PAD]
    float* ws = sm + 64 * PAD;            // [64][PAD]
    float* os = sm + 2 * 64 * PAD;        // [8][64][64]
    const int tid = threadIdx.x;
    const int lg = blockIdx.x;            // 0..7
    const long b0 = (long)blockIdx.y * TB;
    const int ty = tid >> 4, tx = tid & 15;

    for (int ll = 0; ll < 8; ll++) {
        const int l = lg * 8 + ll;
        for (int e = tid; e < 4096; e += 256) {
            int b = e >> 6, rr = e & 63;
            ts[b * PAD + rr] = g_t[(b0 + b) * 4096 + l * 64 + rr];
            ws[b * PAD + rr] = g_Lq[l * 4096 + e];     // ws[s][r]
        }
        __syncthreads();

        float acc[4][4] = {};
        #pragma unroll 4
        for (int r = 0; r < 64; r++) {
            float tv[4], wv[4];
            #pragma unroll
            for (int i = 0; i < 4; i++) tv[i] = ts[(ty * 4 + i) * PAD + r];
            #pragma unroll
            for (int j = 0; j < 4; j++) wv[j] = ws[(tx * 4 + j) * PAD + r];
            #pragma unroll
            for (int i = 0; i < 4; i++)
                #pragma unroll
                for (int j = 0; j < 4; j++) acc[i][j] += tv[i] * wv[j];
        }
        #pragma unroll
        for (int i = 0; i < 4; i++)
            #pragma unroll
            for (int j = 0; j < 4; j++)
                os[ll * 4096 + (ty * 4 + i) * 64 + (tx * 4 + j)] = acc[i][j];
        __syncthreads();
    }

    for (int e = tid; e < 4096; e += 256) {
        int b = e >> 6, s = e & 63;
        float v[8];
        #pragma unroll
        for (int k = 0; k < 8; k++) v[k] = os[k * 4096 + e];
        float* dst = &y[(b0 + b) * 4096 + s * 64 + lg * 8];
        *(float4*)dst       = make_float4(v[0], v[1], v[2], v[3]);
        *(float4*)(dst + 4) = make_float4(v[4], v[5], v[6], v[7]);
    }
}

// ---------------------------------------------------------------------------
extern "C" void kernel_launch(void* const* d_in, const int* in_sizes, int n_in,
                              void* d_out, int out_size) {
    const float* x = (const float*)d_in[0];
    const float* L = (const float*)d_in[1];
    const float* R = (const float*)d_in[2];
    float* y = (float*)d_out;

    const int smem_bytes = (2 * 64 * PAD + 8 * 4096) * sizeof(float); // 164352
    cudaFuncSetAttribute(stage1_kernel,
                         cudaFuncAttributeMaxDynamicSharedMemorySize, smem_bytes);
    cudaFuncSetAttribute(stage2_kernel,
                         cudaFuncAttributeMaxDynamicSharedMemorySize, smem_bytes);

    cayley_kernel<<<128, 256>>>(L, R);
    stage1_kernel<<<dim3(8, 16384 / TB), 256, smem_bytes>>>(x);
    stage2_kernel<<<dim3(8, 16384 / TB), 256, smem_bytes>>>(y);
}

// round 2
// speedup vs baseline: 1.2734x; 1.2734x over previous
#include <cuda_runtime.h>
#include <cuda_bf16.h>
#include <mma.h>

using namespace nvcuda;

// ---------------------------------------------------------------------------
// GSOrthogonal: y = butterfly(x, cayley(R), cayley(L))
// Round 2: tensor cores. Each 64x64 block GEMM done as 3-term bf16 split
// (a_hi*b_hi + a_lo*b_hi + a_hi*b_lo, fp32 accumulate) => ~2^-17 precision.
// ---------------------------------------------------------------------------

#define TB 64      // batch rows per CTA tile
#define RG 4       // r-blocks (or l-blocks) per CTA

__device__ float g_Lq[64 * 64 * 64];
__device__ float g_Rq[64 * 64 * 64];
__device__ float g_t[(long)16384 * 4096];   // intermediate, [b][l][r] layout

// ---------------- Cayley: Q = (I+S)(I-S)^{-1},  S = 0.5(A - A^T) ------------
__global__ __launch_bounds__(256) void cayley_kernel(
    const float* __restrict__ Lin, const float* __restrict__ Rin) {
    __shared__ float aug[64][132];              // 128 active cols + pad
    const int blk = blockIdx.x;                 // 0..63 -> L, 64..127 -> R
    const float* A = blk < 64 ? Lin + blk * 4096 : Rin + (blk - 64) * 4096;
    float* Q = blk < 64 ? g_Lq + blk * 4096 : g_Rq + (blk - 64) * 4096;
    const int tid = threadIdx.x;

    for (int e = tid; e < 4096; e += 256) {
        int i = e >> 6, j = e & 63;
        float s = 0.5f * (A[i * 64 + j] - A[j * 64 + i]);
        float d = (i == j) ? 1.0f : 0.0f;
        aug[i][j] = d + s;           // C   = I + S
        aug[i][64 + j] = d - s;      // RHS = I - S
    }
    __syncthreads();

    const int r  = tid >> 2;         // 4 threads per row
    const int c0 = (tid & 3) * 32;   // 32-column chunk
    for (int col = 0; col < 64; col++) {
        // row `col` is never written during iteration `col`; aug[r][col] is
        // written this iteration only by a same-warp sibling -> syncwarp
        float fac = __fdividef(aug[r][col], aug[col][col]);
        __syncwarp();
        if (r != col) {
            float4*       m = (float4*)&aug[r][c0];
            const float4* p = (const float4*)&aug[col][c0];
            #pragma unroll
            for (int jj = 0; jj < 8; jj++) {
                float4 a = m[jj], b = p[jj];
                a.x -= fac * b.x; a.y -= fac * b.y;
                a.z -= fac * b.z; a.w -= fac * b.w;
                m[jj] = a;
            }
        }
        __syncthreads();
    }
    // Y[i][j] = aug[i][64+j]/aug[i][i]; Q = Y^T
    for (int e = tid; e < 4096; e += 256) {
        int a = e >> 6, b = e & 63;
        Q[a * 64 + b] = __fdividef(aug[b][64 + a], aug[b][b]);
    }
}

// ---------------- bf16 hi/lo split staging ----------------------------------
__device__ __forceinline__ void split_store(__nv_bfloat16* hi, __nv_bfloat16* lo,
                                            int f, float4 v) {
    __nv_bfloat16 hx = __float2bfloat16(v.x);
    __nv_bfloat16 hy = __float2bfloat16(v.y);
    __nv_bfloat16 hz = __float2bfloat16(v.z);
    __nv_bfloat16 hw = __float2bfloat16(v.w);
    __nv_bfloat16 lx = __float2bfloat16(v.x - __bfloat162float(hx));
    __nv_bfloat16 ly = __float2bfloat16(v.y - __bfloat162float(hy));
    __nv_bfloat16 lz = __float2bfloat16(v.z - __bfloat162float(hz));
    __nv_bfloat16 lw = __float2bfloat16(v.w - __bfloat162float(hw));
    ((__nv_bfloat162*)hi)[f * 2 + 0] = __halves2bfloat162(hx, hy);
    ((__nv_bfloat162*)hi)[f * 2 + 1] = __halves2bfloat162(hz, hw);
    ((__nv_bfloat162*)lo)[f * 2 + 0] = __halves2bfloat162(lx, ly);
    ((__nv_bfloat162*)lo)[f * 2 + 1] = __halves2bfloat162(lz, lw);
}

// 64x64 x 64x64^T block GEMM, 3-term bf16 split, acc in ts (row-major 64x64).
// A: xs (m=row, k contiguous, ld 64). B: ws (n-major storage -> col_major ld 64).
__device__ __forceinline__ void block_gemm_3bf16(
    const __nv_bfloat16* xs_hi, const __nv_bfloat16* xs_lo,
    const __nv_bfloat16* ws_hi, const __nv_bfloat16* ws_lo,
    float* out, int mi, int nb) {
    wmma::fragment<wmma::accumulator, 16, 16, 16, float> acc[2];
    wmma::fill_fragment(acc[0], 0.0f);
    wmma::fill_fragment(acc[1], 0.0f);
    #pragma unroll
    for (int kk = 0; kk < 4; kk++) {
        wmma::fragment<wmma::matrix_a, 16, 16, 16, __nv_bfloat16, wmma::row_major> ah, al;
        wmma::load_matrix_sync(ah, xs_hi + mi * 1024 + kk * 16, 64);
        wmma::load_matrix_sync(al, xs_lo + mi * 1024 + kk * 16, 64);
        #pragma unroll
        for (int j = 0; j < 2; j++) {
            wmma::fragment<wmma::matrix_b, 16, 16, 16, __nv_bfloat16, wmma::col_major> bh, bl;
            wmma::load_matrix_sync(bh, ws_hi + (nb + j) * 1024 + kk * 16, 64);
            wmma::load_matrix_sync(bl, ws_lo + (nb + j) * 1024 + kk * 16, 64);
            wmma::mma_sync(acc[j], ah, bh, acc[j]);
            wmma::mma_sync(acc[j], al, bh, acc[j]);
            wmma::mma_sync(acc[j], ah, bl, acc[j]);
        }
    }
    wmma::store_matrix_sync(out + mi * 1024 + (nb + 0) * 16, acc[0], 64, wmma::mem_row_major);
    wmma::store_matrix_sync(out + mi * 1024 + (nb + 1) * 16, acc[1], 64, wmma::mem_row_major);
}

// ---------------- Stage 1: t[b][l][r] = sum_p Rq[r][l][p] * x[b][r*64+p] -----
__global__ __launch_bounds__(256) void stage1_kernel(const float* __restrict__ x) {
    extern __shared__ char smraw[];
    __nv_bfloat16* xs_hi = (__nv_bfloat16*)smraw;
    __nv_bfloat16* xs_lo = xs_hi + 4096;
    __nv_bfloat16* ws_hi = xs_lo + 4096;
    __nv_bfloat16* ws_lo = ws_hi + 4096;
    float* ts = (float*)(ws_lo + 4096);          // [RG][64][64]

    const int tid = threadIdx.x;
    const int rg = blockIdx.x;                   // 0..15
    const long b0 = (long)blockIdx.y * TB;
    const int wid = tid >> 5;
    const int mi = wid & 3;
    const int nb = (wid >> 2) << 1;

    float4 xbuf[4], wbuf[4];
    {   // prefetch rr=0
        const int rblk = rg * RG;
        #pragma unroll
        for (int q = 0; q < 4; q++) {
            int f = q * 256 + tid, b = f >> 4, p4 = f & 15;
            xbuf[q] = ((const float4*)(x + (b0 + b) * 4096 + rblk * 64))[p4];
            wbuf[q] = ((const float4*)(g_Rq + rblk * 4096))[f];
        }
    }

    for (int rr = 0; rr < RG; rr++) {
        __syncthreads();                          // prior frag reads complete
        #pragma unroll
        for (int q = 0; q < 4; q++) {
            int f = q * 256 + tid;
            split_store(xs_hi, xs_lo, f, xbuf[q]);
            split_store(ws_hi, ws_lo, f, wbuf[q]);
        }
        __syncthreads();
        if (rr + 1 < RG) {                        // prefetch next, overlaps MMA
            const int rblk = rg * RG + rr + 1;
            #pragma unroll
            for (int q = 0; q < 4; q++) {
                int f = q * 256 + tid, b = f >> 4, p4 = f & 15;
                xbuf[q] = ((const float4*)(x + (b0 + b) * 4096 + rblk * 64))[p4];
                wbuf[q] = ((const float4*)(g_Rq + rblk * 4096))[f];
            }
        }
        block_gemm_3bf16(xs_hi, xs_lo, ws_hi, ws_lo, ts + rr * 4096, mi, nb);
    }
    __syncthreads();

    // transposed write: t[b][l][rg*4 .. +3] as one aligned float4 (16B granule)
    for (int e = tid; e < 4096; e += 256) {
        int b = e >> 6, l = e & 63;
        float4 v = make_float4(ts[e], ts[4096 + e], ts[8192 + e], ts[12288 + e]);
        *(float4*)(&g_t[(b0 + b) * 4096 + l * 64 + rg * 4]) = v;
    }
}

// ---------------- Stage 2: y[b][s*64+l] = sum_r Lq[l][s][r] * t[b][l][r] -----
__global__ __launch_bounds__(256) void stage2_kernel(float* __restrict__ y) {
    extern __shared__ char smraw[];
    __nv_bfloat16* xs_hi = (__nv_bfloat16*)smraw;
    __nv_bfloat16* xs_lo = xs_hi + 4096;
    __nv_bfloat16* ws_hi = xs_lo + 4096;
    __nv_bfloat16* ws_lo = ws_hi + 4096;
    float* ts = (float*)(ws_lo + 4096);          // [RG][64][64]

    const int tid = threadIdx.x;
    const int lg = blockIdx.x;                   // 0..15
    const long b0 = (long)blockIdx.y * TB;
    const int wid = tid >> 5;
    const int mi = wid & 3;
    const int nb = (wid >> 2) << 1;

    float4 xbuf[4], wbuf[4];
    {   // prefetch ll=0
        const int l = lg * RG;
        #pragma unroll
        for (int q = 0; q < 4; q++) {
            int f = q * 256 + tid, b = f >> 4, p4 = f & 15;
            xbuf[q] = ((const float4*)(g_t + (b0 + b) * 4096 + l * 64))[p4];
            wbuf[q] = ((const float4*)(g_Lq + l * 4096))[f];
        }
    }

    for (int ll = 0; ll < RG; ll++) {
        __syncthreads();
        #pragma unroll
        for (int q = 0; q < 4; q++) {
            int f = q * 256 + tid;
            split_store(xs_hi, xs_lo, f, xbuf[q]);
            split_store(ws_hi, ws_lo, f, wbuf[q]);
        }
        __syncthreads();
        if (ll + 1 < RG) {
            const int l = lg * RG + ll + 1;
            #pragma unroll
            for (int q = 0; q < 4; q++) {
                int f = q * 256 + tid, b = f >> 4, p4 = f & 15;
                xbuf[q] = ((const float4*)(g_t + (b0 + b) * 4096 + l * 64))[p4];
                wbuf[q] = ((const float4*)(g_Lq + l * 4096))[f];
            }
        }
        block_gemm_3bf16(xs_hi, xs_lo, ws_hi, ws_lo, ts + ll * 4096, mi, nb);
    }
    __syncthreads();

    // y[b][s*64 + lg*4 .. +3] as one aligned float4
    for (int e = tid; e < 4096; e += 256) {
        int b = e >> 6, s = e & 63;
        float4 v = make_float4(ts[e], ts[4096 + e], ts[8192 + e], ts[12288 + e]);
        *(float4*)(&y[(b0 + b) * 4096 + s * 64 + lg * 4]) = v;
    }
}

// ---------------------------------------------------------------------------
extern "C" void kernel_launch(void* const* d_in, const int* in_sizes, int n_in,
                              void* d_out, int out_size) {
    const float* x = (const float*)d_in[0];
    const float* L = (const float*)d_in[1];
    const float* R = (const float*)d_in[2];
    float* y = (float*)d_out;

    const int smem_bytes = 4 * 4096 * 2 + RG * 4096 * 4;   // 98304 B
    cudaFuncSetAttribute(stage1_kernel,
                         cudaFuncAttributeMaxDynamicSharedMemorySize, smem_bytes);
    cudaFuncSetAttribute(stage2_kernel,
                         cudaFuncAttributeMaxDynamicSharedMemorySize, smem_bytes);

    cayley_kernel<<<128, 256>>>(L, R);
    stage1_kernel<<<dim3(16, 16384 / TB), 256, smem_bytes>>>(x);
    stage2_kernel<<<dim3(16, 16384 / TB), 256, smem_bytes>>>(y);
}

// round 3
// speedup vs baseline: 2.7583x; 2.1660x over previous
#include <cuda_runtime.h>
#include <cuda_bf16.h>
#include <mma.h>

using namespace nvcuda;

// ---------------------------------------------------------------------------
// GSOrthogonal round 3:
//  - cayley: 1 warp / matrix, zero CTA barriers (round-2 was BAR/STS-drain bound)
//  - stages: bf16 3-term split GEMM, padded smem (LDSM conflict-free),
//    32x32 warp tiles, g_t relaid to [l][r][b] so stage1 stores acc directly
//    to global (full-sector col_major stores) and stage2 reads coalesced.
// ---------------------------------------------------------------------------

#define S1_TB 128
#define S1_RG 4
#define S2_TB 64
#define S2_LG 4
#define LDH   72            // bf16 smem row stride (144B -> conflict-free LDSM)

__device__ float g_Lq[64 * 64 * 64];
__device__ float g_Rq[64 * 64 * 64];
__device__ float g_t[(size_t)4096 * 16384];   // layout [l][r][b]

// ---------------- Cayley: Q = (I+S)(I-S)^{-1}, one warp per matrix ----------
__global__ __launch_bounds__(32) void cayley_kernel(
    const float* __restrict__ Lin, const float* __restrict__ Rin) {
    __shared__ float aug[64][132];
    const int blk = blockIdx.x;                 // 0..63 -> L, 64..127 -> R
    const float* A = blk < 64 ? Lin + blk * 4096 : Rin + (blk - 64) * 4096;
    float* Q = blk < 64 ? g_Lq + blk * 4096 : g_Rq + (blk - 64) * 4096;
    const int lane = threadIdx.x;

    for (int e = lane; e < 4096; e += 32) {
        int i = e >> 6, j = e & 63;
        float s = 0.5f * (A[i * 64 + j] - A[j * 64 + i]);
        float d = (i == j) ? 1.0f : 0.0f;
        aug[i][j] = d + s;           // I + S
        aug[i][64 + j] = d - s;      // I - S
    }
    __syncwarp();

    const int r0 = lane * 2, r1 = lane * 2 + 1;
    for (int col = 0; col < 64; col++) {
        float piv = __fdividef(1.0f, aug[col][col]);
        float f0 = aug[r0][col] * piv;
        float f1 = aug[r1][col] * piv;
        bool u0 = (r0 != col), u1 = (r1 != col);
        __syncwarp();
        const float4* p4 = (const float4*)&aug[col][0];
        float4* m0 = (float4*)&aug[r0][0];
        float4* m1 = (float4*)&aug[r1][0];
        #pragma unroll
        for (int j = 0; j < 32; j++) {
            float4 p = p4[j];
            float4 a = m0[j];
            a.x -= f0 * p.x; a.y -= f0 * p.y; a.z -= f0 * p.z; a.w -= f0 * p.w;
            if (u0) m0[j] = a;
            float4 b = m1[j];
            b.x -= f1 * p.x; b.y -= f1 * p.y; b.z -= f1 * p.z; b.w -= f1 * p.w;
            if (u1) m1[j] = b;
        }
        __syncwarp();
    }
    for (int e = lane; e < 4096; e += 32) {
        int a = e >> 6, b = e & 63;
        Q[a * 64 + b] = __fdividef(aug[b][64 + a], aug[b][b]);
    }
}

// ---------------- bf16 hi/lo split store (4 values) -------------------------
__device__ __forceinline__ void split4(__nv_bfloat16* hi, __nv_bfloat16* lo,
                                       int idx, float4 v) {
    __nv_bfloat16 hx = __float2bfloat16(v.x), hy = __float2bfloat16(v.y);
    __nv_bfloat16 hz = __float2bfloat16(v.z), hw = __float2bfloat16(v.w);
    __nv_bfloat16 lx = __float2bfloat16(v.x - __bfloat162float(hx));
    __nv_bfloat16 ly = __float2bfloat16(v.y - __bfloat162float(hy));
    __nv_bfloat16 lz = __float2bfloat16(v.z - __bfloat162float(hz));
    __nv_bfloat16 lw = __float2bfloat16(v.w - __bfloat162float(hw));
    *(__nv_bfloat162*)(hi + idx)     = __halves2bfloat162(hx, hy);
    *(__nv_bfloat162*)(hi + idx + 2) = __halves2bfloat162(hz, hw);
    *(__nv_bfloat162*)(lo + idx)     = __halves2bfloat162(lx, ly);
    *(__nv_bfloat162*)(lo + idx + 2) = __halves2bfloat162(lz, lw);
}

// ---------------- Stage 1: g_t[l][r][b] = sum_p Rq[r][l][p] x[b][r*64+p] ----
__global__ __launch_bounds__(256, 2) void stage1_kernel(const float* __restrict__ x) {
    extern __shared__ __nv_bfloat16 sm1[];
    __nv_bfloat16* xs_hi = sm1;                    // [128][LDH]
    __nv_bfloat16* xs_lo = xs_hi + 128 * LDH;
    __nv_bfloat16* wsb   = xs_lo + 128 * LDH;      // [RG][2][64*LDH]

    const int tid = threadIdx.x;
    const int rg = blockIdx.x;                     // 0..15
    const long b0 = (long)blockIdx.y * S1_TB;
    const int wid = tid >> 5;
    const int wm = wid & 3;                        // m block (32 b-rows)
    const int wn = wid >> 2;                       // n block (32 l-cols)

    // preload all RG weight blocks, split to bf16 hi/lo
    for (int rr = 0; rr < S1_RG; rr++) {
        const float4* wp = (const float4*)(g_Rq + (size_t)(rg * S1_RG + rr) * 4096);
        __nv_bfloat16* whi = wsb + rr * 2 * 64 * LDH;
        __nv_bfloat16* wlo = whi + 64 * LDH;
        #pragma unroll
        for (int q = 0; q < 4; q++) {
            int f = q * 256 + tid;                 // 0..1023
            int l = f >> 4, p4 = f & 15;
            split4(whi, wlo, l * LDH + p4 * 4, wp[f]);
        }
    }

    // prefetch x tile for rr = 0
    float4 xbuf[8];
    #pragma unroll
    for (int q = 0; q < 8; q++) {
        int f = q * 256 + tid;                     // 0..2047
        int b = f >> 4, p4 = f & 15;
        xbuf[q] = *(const float4*)(x + (b0 + b) * 4096 + (rg * S1_RG) * 64 + p4 * 4);
    }

    for (int rr = 0; rr < S1_RG; rr++) {
        #pragma unroll
        for (int q = 0; q < 8; q++) {
            int f = q * 256 + tid;
            int b = f >> 4, p4 = f & 15;
            split4(xs_hi, xs_lo, b * LDH + p4 * 4, xbuf[q]);
        }
        __syncthreads();
        if (rr + 1 < S1_RG) {                      // prefetch next (overlaps MMA)
            #pragma unroll
            for (int q = 0; q < 8; q++) {
                int f = q * 256 + tid;
                int b = f >> 4, p4 = f & 15;
                xbuf[q] = *(const float4*)(x + (b0 + b) * 4096 +
                                           (rg * S1_RG + rr + 1) * 64 + p4 * 4);
            }
        }

        const __nv_bfloat16* whi = wsb + rr * 2 * 64 * LDH;
        const __nv_bfloat16* wlo = whi + 64 * LDH;
        wmma::fragment<wmma::accumulator, 16, 16, 16, float> acc[2][2];
        #pragma unroll
        for (int i = 0; i < 2; i++)
            #pragma unroll
            for (int j = 0; j < 2; j++) wmma::fill_fragment(acc[i][j], 0.0f);

        #pragma unroll
        for (int kk = 0; kk < 4; kk++) {
            wmma::fragment<wmma::matrix_a, 16, 16, 16, __nv_bfloat16, wmma::row_major> ah[2], al[2];
            wmma::fragment<wmma::matrix_b, 16, 16, 16, __nv_bfloat16, wmma::col_major> bh[2], bl[2];
            #pragma unroll
            for (int i = 0; i < 2; i++) {
                wmma::load_matrix_sync(ah[i], xs_hi + (wm * 32 + i * 16) * LDH + kk * 16, LDH);
                wmma::load_matrix_sync(al[i], xs_lo + (wm * 32 + i * 16) * LDH + kk * 16, LDH);
            }
            #pragma unroll
            for (int j = 0; j < 2; j++) {
                wmma::load_matrix_sync(bh[j], whi + (wn * 32 + j * 16) * LDH + kk * 16, LDH);
                wmma::load_matrix_sync(bl[j], wlo + (wn * 32 + j * 16) * LDH + kk * 16, LDH);
            }
            #pragma unroll
            for (int i = 0; i < 2; i++)
                #pragma unroll
                for (int j = 0; j < 2; j++) {
                    wmma::mma_sync(acc[i][j], ah[i], bh[j], acc[i][j]);
                    wmma::mma_sync(acc[i][j], al[i], bh[j], acc[i][j]);
                    wmma::mma_sync(acc[i][j], ah[i], bl[j], acc[i][j]);
                }
        }

        // direct global store: g_t[l][r][b], col_major (b contiguous)
        const int rblk = rg * S1_RG + rr;
        #pragma unroll
        for (int i = 0; i < 2; i++)
            #pragma unroll
            for (int j = 0; j < 2; j++) {
                float* ptr = g_t + ((size_t)(wn * 32 + j * 16) * 64 + rblk) * 16384
                                 + b0 + wm * 32 + i * 16;
                wmma::store_matrix_sync(ptr, acc[i][j], 64u * 16384u, wmma::mem_col_major);
            }
        __syncthreads();
    }
}

// ---------------- Stage 2: y[b][s*64+l] = sum_r g_t[l][r][b] Lq[l][s][r] ----
__global__ __launch_bounds__(256, 2) void stage2_kernel(float* __restrict__ y) {
    extern __shared__ __nv_bfloat16 sm2[];
    __nv_bfloat16* ts_hi = sm2;                    // [64 r][LDH b] (A col-major)
    __nv_bfloat16* ts_lo = ts_hi + 64 * LDH;
    __nv_bfloat16* ws_hi = ts_lo + 64 * LDH;       // [64 s][LDH r]
    __nv_bfloat16* ws_lo = ws_hi + 64 * LDH;
    float* os = (float*)(ws_lo + 64 * LDH);        // [LG][64 b][64 s]

    const int tid = threadIdx.x;
    const int lg = blockIdx.x;                     // 0..15
    const long b0 = (long)blockIdx.y * S2_TB;
    const int wid = tid >> 5;
    const int wm = wid & 3;                        // m block (16 b-rows)
    const int wn = wid >> 2;                       // n block (32 s-cols)

    float4 tbuf[4], wbuf[4];
    #pragma unroll
    for (int q = 0; q < 4; q++) {                  // prefetch ll = 0
        int f = q * 256 + tid;                     // 0..1023
        int r = f >> 4, c4 = f & 15;
        tbuf[q] = *(const float4*)(g_t + ((size_t)(lg * S2_LG) * 64 + r) * 16384
                                       + b0 + c4 * 4);
        wbuf[q] = ((const float4*)(g_Lq + (size_t)(lg * S2_LG) * 4096))[f];
    }

    for (int ll = 0; ll < S2_LG; ll++) {
        #pragma unroll
        for (int q = 0; q < 4; q++) {
            int f = q * 256 + tid;
            int rr = f >> 4, c4 = f & 15;
            split4(ts_hi, ts_lo, rr * LDH + c4 * 4, tbuf[q]);   // ts[r][b]
            split4(ws_hi, ws_lo, rr * LDH + c4 * 4, wbuf[q]);   // ws[s][r]
        }
        __syncthreads();
        if (ll + 1 < S2_LG) {
            const int l = lg * S2_LG + ll + 1;
            #pragma unroll
            for (int q = 0; q < 4; q++) {
                int f = q * 256 + tid;
                int r = f >> 4, c4 = f & 15;
                tbuf[q] = *(const float4*)(g_t + ((size_t)l * 64 + r) * 16384
                                               + b0 + c4 * 4);
                wbuf[q] = ((const float4*)(g_Lq + (size_t)l * 4096))[f];
            }
        }

        wmma::fragment<wmma::accumulator, 16, 16, 16, float> acc[2];
        wmma::fill_fragment(acc[0], 0.0f);
        wmma::fill_fragment(acc[1], 0.0f);
        #pragma unroll
        for (int kk = 0; kk < 4; kk++) {
            wmma::fragment<wmma::matrix_a, 16, 16, 16, __nv_bfloat16, wmma::col_major> ah, al;
            wmma::fragment<wmma::matrix_b, 16, 16, 16, __nv_bfloat16, wmma::col_major> bh[2], bl[2];
            wmma::load_matrix_sync(ah, ts_hi + kk * 16 * LDH + wm * 16, LDH);
            wmma::load_matrix_sync(al, ts_lo + kk * 16 * LDH + wm * 16, LDH);
            #pragma unroll
            for (int j = 0; j < 2; j++) {
                wmma::load_matrix_sync(bh[j], ws_hi + (wn * 32 + j * 16) * LDH + kk * 16, LDH);
                wmma::load_matrix_sync(bl[j], ws_lo + (wn * 32 + j * 16) * LDH + kk * 16, LDH);
                wmma::mma_sync(acc[j], ah, bh[j], acc[j]);
                wmma::mma_sync(acc[j], al, bh[j], acc[j]);
                wmma::mma_sync(acc[j], ah, bl[j], acc[j]);
            }
        }
        #pragma unroll
        for (int j = 0; j < 2; j++)
            wmma::store_matrix_sync(os + ll * 4096 + (wm * 16) * 64 + wn * 32 + j * 16,
                                    acc[j], 64, wmma::mem_row_major);
        __syncthreads();
    }

    // gather LG l-values per (b,s): one aligned float4 per output granule
    for (int e = tid; e < 4096; e += 256) {
        int b = e >> 6, s = e & 63;
        float4 v = make_float4(os[e], os[4096 + e], os[8192 + e], os[12288 + e]);
        *(float4*)(y + (b0 + b) * 4096 + s * 64 + lg * S2_LG) = v;
    }
}

// ---------------------------------------------------------------------------
extern "C" void kernel_launch(void* const* d_in, const int* in_sizes, int n_in,
                              void* d_out, int out_size) {
    const float* x = (const float*)d_in[0];
    const float* L = (const float*)d_in[1];
    const float* R = (const float*)d_in[2];
    float* y = (float*)d_out;

    const int smem1 = (2 * 128 * LDH + S1_RG * 2 * 64 * LDH) * 2;      // 110592
    const int smem2 = 4 * 64 * LDH * 2 + S2_LG * 4096 * 4;             // 102400
    cudaFuncSetAttribute(stage1_kernel,
                         cudaFuncAttributeMaxDynamicSharedMemorySize, smem1);
    cudaFuncSetAttribute(stage2_kernel,
                         cudaFuncAttributeMaxDynamicSharedMemorySize, smem2);

    cayley_kernel<<<128, 32>>>(L, R);
    stage1_kernel<<<dim3(16, 16384 / S1_TB), 256, smem1>>>(x);
    stage2_kernel<<<dim3(16, 16384 / S2_TB), 256, smem2>>>(y);
}

// round 6
// speedup vs baseline: 3.1601x; 1.1457x over previous
#include <cuda_runtime.h>
#include <cuda_bf16.h>

// ---------------------------------------------------------------------------
// GSOrthogonal round 6: hand-rolled mma.sync (HMMA) — tcgen05 unavailable
// (harness PTX targets compute_103, no 'a' features).
//  stage1: g_t[l][r][b] = sum_p Rq[r][l][p] x[b][r*64+p], packed bf16 hi/lo
//  stage2: y[b][s*64+l] = sum_r Lq[l][s][r] t[l][r][b]
//  3-term bf16 split (hi*hi + lo*hi + hi*lo), fp32 accumulate.
// ---------------------------------------------------------------------------

__device__ float g_Lq[64 * 64 * 64];
__device__ float g_Rq[64 * 64 * 64];
__device__ unsigned g_t[(size_t)4096 * 16384];   // [l][r][b], u32 = hi | lo<<16

__device__ __forceinline__ unsigned smem_u32(const void* p) {
    unsigned a;
    asm("{ .reg .u64 t; cvta.to.shared.u64 t, %1; cvt.u32.u64 %0, t; }"
        : "=r"(a) : "l"(p));
    return a;
}

// XOR swizzle: 16B chunk index ^= row&7 (rows are 128B)
#define SWZ(o) ((o) ^ (((o) >> 3) & 0x70u))

#define LDSM4(r0, r1, r2, r3, addr)                                           \
    asm volatile("ldmatrix.sync.aligned.m8n8.x4.shared.b16 {%0,%1,%2,%3},[%4];" \
        : "=r"(r0), "=r"(r1), "=r"(r2), "=r"(r3) : "r"(addr))
#define LDSM4T(r0, r1, r2, r3, addr)                                          \
    asm volatile("ldmatrix.sync.aligned.m8n8.x4.trans.shared.b16 {%0,%1,%2,%3},[%4];" \
        : "=r"(r0), "=r"(r1), "=r"(r2), "=r"(r3) : "r"(addr))
#define MMA(d, a, b0, b1)                                                     \
    asm volatile("mma.sync.aligned.m16n8k16.row.col.f32.bf16.bf16.f32 "       \
        "{%0,%1,%2,%3},{%4,%5,%6,%7},{%8,%9},{%0,%1,%2,%3};"                  \
        : "+f"((d)[0]), "+f"((d)[1]), "+f"((d)[2]), "+f"((d)[3])              \
        : "r"((a)[0]), "r"((a)[1]), "r"((a)[2]), "r"((a)[3]), "r"(b0), "r"(b1))

__device__ __forceinline__ unsigned pack2(__nv_bfloat16 a, __nv_bfloat16 b) {
    return (unsigned)__bfloat16_as_ushort(a) |
           ((unsigned)__bfloat16_as_ushort(b) << 16);
}
// float -> (hi bf16 | lo bf16 << 16)
__device__ __forceinline__ unsigned packf(float v) {
    __nv_bfloat16 h = __float2bfloat16(v);
    __nv_bfloat16 l = __float2bfloat16(v - __bfloat162float(h));
    return pack2(h, l);
}
// split float4 into hi/lo bf16 quads, store as two 8B STS (conflict-free w/ SWZ)
__device__ __forceinline__ void split_sts(char* bh, char* bl, unsigned off,
                                          float4 v) {
    __nv_bfloat16 hx = __float2bfloat16(v.x), hy = __float2bfloat16(v.y);
    __nv_bfloat16 hz = __float2bfloat16(v.z), hw = __float2bfloat16(v.w);
    __nv_bfloat16 lx = __float2bfloat16(v.x - __bfloat162float(hx));
    __nv_bfloat16 ly = __float2bfloat16(v.y - __bfloat162float(hy));
    __nv_bfloat16 lz = __float2bfloat16(v.z - __bfloat162float(hz));
    __nv_bfloat16 lw = __float2bfloat16(v.w - __bfloat162float(hw));
    unsigned sw = SWZ(off);
    *(uint2*)(bh + sw) = make_uint2(pack2(hx, hy), pack2(hz, hw));
    *(uint2*)(bl + sw) = make_uint2(pack2(lx, ly), pack2(lz, lw));
}
// unpack 4 packed g_t elements -> hi/lo quads
__device__ __forceinline__ void unpack_sts(char* bh, char* bl, unsigned off,
                                           uint4 u) {
    unsigned sw = SWZ(off);
    *(uint2*)(bh + sw) = make_uint2((u.x & 0xffffu) | (u.y << 16),
                                    (u.z & 0xffffu) | (u.w << 16));
    *(uint2*)(bl + sw) = make_uint2((u.x >> 16) | (u.y & 0xffff0000u),
                                    (u.z >> 16) | (u.w & 0xffff0000u));
}

// ---------------- Cayley: swizzled conflict-free GJ, 1 warp / matrix --------
__device__ __forceinline__ float4* aug4(float* a, int r, int c4) {
    return (float4*)a + r * 32 + (c4 ^ (r & 31));
}
__device__ __forceinline__ float augS(float* a, int r, int c) {
    return ((float*)aug4(a, r, c >> 2))[c & 3];
}

__global__ __launch_bounds__(32) void cayley_kernel(
    const float* __restrict__ Lin, const float* __restrict__ Rin) {
    __shared__ float aug[64 * 128];
    const int blk = blockIdx.x;
    const float* A = blk < 64 ? Lin + blk * 4096 : Rin + (blk - 64) * 4096;
    float* Q = blk < 64 ? g_Lq + blk * 4096 : g_Rq + (blk - 64) * 4096;
    const int lane = threadIdx.x;
    const int r0 = lane, r1 = lane + 32;

    #pragma unroll
    for (int h = 0; h < 2; h++) {
        int r = h ? r1 : r0;
        for (int c4 = 0; c4 < 32; c4++) {
            float4 v;
            #pragma unroll
            for (int q = 0; q < 4; q++) {
                int j = (c4 << 2) + q;
                int jj = j & 63;
                float s = 0.5f * (A[r * 64 + jj] - A[jj * 64 + r]);
                float d = (r == jj) ? 1.0f : 0.0f;
                ((float*)&v)[q] = (j < 64) ? d + s : d - s;   // I+S | I-S
            }
            *aug4(aug, r, c4) = v;
        }
    }
    __syncwarp();

    for (int col = 0; col < 64; col++) {
        float piv = __fdividef(1.0f, augS(aug, col, col));
        float f0 = augS(aug, r0, col) * piv;
        float f1 = augS(aug, r1, col) * piv;
        bool u0 = (r0 != col), u1 = (r1 != col);
        __syncwarp();
        #pragma unroll 4
        for (int c4 = col >> 2; c4 < 32; c4++) {
            float4 p = *aug4(aug, col, c4);
            float4 a = *aug4(aug, r0, c4);
            a.x -= f0 * p.x; a.y -= f0 * p.y; a.z -= f0 * p.z; a.w -= f0 * p.w;
            if (u0) *aug4(aug, r0, c4) = a;
            float4 b = *aug4(aug, r1, c4);
            b.x -= f1 * p.x; b.y -= f1 * p.y; b.z -= f1 * p.z; b.w -= f1 * p.w;
            if (u1) *aug4(aug, r1, c4) = b;
        }
        __syncwarp();
    }
    for (int e = lane; e < 4096; e += 32) {
        int a = e >> 6, b = e & 63;          // Q = Y^T, Y = (I+S)^{-1}(I-S)
        Q[a * 64 + b] = __fdividef(augS(aug, b, 64 + a), augS(aug, b, b));
    }
}

// ---------------- Stage 1: M=128(b) N=64(l) K=64(p) -------------------------
// smem: Ahi 0..16K, Alo 16K..32K, Bhi 32K..40K, Blo 40K..48K  (rows 128B SWZ)
#define S1_AHI 0
#define S1_ALO 16384
#define S1_BHI 32768
#define S1_BLO 40960
#define S1_SMEM 49152

__global__ __launch_bounds__(256, 2) void stage1_kernel(const float* __restrict__ x) {
    extern __shared__ char sm[];
    const unsigned sb = smem_u32(sm);
    const int tid = threadIdx.x, wid = tid >> 5, lane = tid & 31;
    const int rblk = blockIdx.x;
    const long b0 = (long)blockIdx.y * 128;

    // A = x tile 128x64 (row=b, 128B rows)
    #pragma unroll
    for (int q = 0; q < 8; q++) {
        int f = q * 256 + tid;
        int row = f >> 4, p4 = f & 15;
        float4 v = *(const float4*)(x + (b0 + row) * 4096 + rblk * 64 + p4 * 4);
        split_sts(sm + S1_AHI, sm + S1_ALO, (unsigned)(row * 128 + p4 * 8), v);
    }
    // B = Rq[rblk] 64x64 (row=l)
    #pragma unroll
    for (int q = 0; q < 4; q++) {
        int f = q * 256 + tid;
        int row = f >> 4, p4 = f & 15;
        float4 v = *(const float4*)(g_Rq + (size_t)rblk * 4096 + row * 64 + p4 * 4);
        split_sts(sm + S1_BHI, sm + S1_BLO, (unsigned)(row * 128 + p4 * 8), v);
    }
    __syncthreads();

    const int wm = wid & 3, wn = wid >> 2;
    const int M0 = wm * 32, N0 = wn * 32;
    float acc[2][4][4] = {};

    #pragma unroll
    for (int kk = 0; kk < 4; kk++) {
        const unsigned kb = kk * 32;
        unsigned ah[2][4], al[2][4];
        #pragma unroll
        for (int mt = 0; mt < 2; mt++) {
            unsigned row = M0 + mt * 16 + (lane & 15);
            unsigned ph = SWZ(row * 128 + kb + ((lane >> 4) << 4));
            LDSM4(ah[mt][0], ah[mt][1], ah[mt][2], ah[mt][3], sb + S1_AHI + ph);
            LDSM4(al[mt][0], al[mt][1], al[mt][2], al[mt][3], sb + S1_ALO + ph);
        }
        unsigned bh[2][4], bl[2][4];
        #pragma unroll
        for (int nh = 0; nh < 2; nh++) {
            unsigned row = N0 + nh * 16 + (lane & 7) + ((lane >> 4) << 3);
            unsigned ph = SWZ(row * 128 + kb + (((lane >> 3) & 1) << 4));
            LDSM4(bh[nh][0], bh[nh][1], bh[nh][2], bh[nh][3], sb + S1_BHI + ph);
            LDSM4(bl[nh][0], bl[nh][1], bl[nh][2], bl[nh][3], sb + S1_BLO + ph);
        }
        #pragma unroll
        for (int mt = 0; mt < 2; mt++)
            #pragma unroll
            for (int nh = 0; nh < 2; nh++) {
                MMA(acc[mt][nh * 2 + 0], ah[mt], bh[nh][0], bh[nh][1]);
                MMA(acc[mt][nh * 2 + 0], al[mt], bh[nh][0], bh[nh][1]);
                MMA(acc[mt][nh * 2 + 0], ah[mt], bl[nh][0], bl[nh][1]);
                MMA(acc[mt][nh * 2 + 1], ah[mt], bh[nh][2], bh[nh][3]);
                MMA(acc[mt][nh * 2 + 1], al[mt], bh[nh][2], bh[nh][3]);
                MMA(acc[mt][nh * 2 + 1], ah[mt], bl[nh][2], bl[nh][3]);
            }
    }

    // epilogue: pack fp32 -> bf16 hi/lo u32, direct STG to g_t[l][r][b]
    const int g = lane >> 2, t2 = (lane & 3) << 1;
    #pragma unroll
    for (int mt = 0; mt < 2; mt++) {
        const long bb = b0 + M0 + mt * 16 + g;
        #pragma unroll
        for (int nt = 0; nt < 4; nt++) {
            int l0 = N0 + nt * 8 + t2;
            size_t base = ((size_t)l0 * 64 + rblk) * 16384;
            g_t[base + bb]               = packf(acc[mt][nt][0]);
            g_t[base + 1048576 + bb]     = packf(acc[mt][nt][1]);   // l0+1
            g_t[base + bb + 8]           = packf(acc[mt][nt][2]);
            g_t[base + 1048576 + bb + 8] = packf(acc[mt][nt][3]);
        }
    }
}

// ---------------- Stage 2: 4 l's per CTA, M=64(b) N=64(s) K=64(r) ----------
// smem: At_hi 0..8K, At_lo 8K..16K (k-major [r][b]), Bhi 16K..24K, Blo 24K..32K,
//       os (float) 32K.. : 4 planes of 64x66
#define S2_ATH 0
#define S2_ATL 8192
#define S2_BH  16384
#define S2_BL  24576
#define S2_OS  32768
#define S2_SMEM (32768 + 4 * 64 * 66 * 4)     // 100352

__global__ __launch_bounds__(256, 2) void stage2_kernel(float* __restrict__ y) {
    extern __shared__ char sm[];
    const unsigned sb = smem_u32(sm);
    float* os = (float*)(sm + S2_OS);
    const int tid = threadIdx.x, wid = tid >> 5, lane = tid & 31;
    const int lg = blockIdx.x;                    // 0..15
    const long b0 = (long)blockIdx.y * 64;

    const int wm = wid & 1, wn = wid >> 1;        // warp tile m32 x n16
    const int M0 = wm * 32, N0 = wn * 16;
    const int g = lane >> 2, t2 = (lane & 3) << 1;

    uint4 abuf[4];
    float4 wbuf[4];
    #pragma unroll
    for (int q = 0; q < 4; q++) {                 // prefetch ll=0
        int f = q * 256 + tid;
        int r = f >> 4, b4 = f & 15;
        abuf[q] = *(const uint4*)(g_t + ((size_t)(lg * 4) * 64 + r) * 16384
                                      + b0 + b4 * 4);
        wbuf[q] = *(const float4*)(g_Lq + (size_t)(lg * 4) * 4096 + f * 4);
    }

    for (int ll = 0; ll < 4; ll++) {
        #pragma unroll
        for (int q = 0; q < 4; q++) {
            int f = q * 256 + tid;
            int r = f >> 4, b4 = f & 15;
            unpack_sts(sm + S2_ATH, sm + S2_ATL, (unsigned)(r * 128 + b4 * 8),
                       abuf[q]);                   // At[r][b]
            split_sts(sm + S2_BH, sm + S2_BL, (unsigned)(r * 128 + b4 * 8),
                      wbuf[q]);                    // W[s][r]
        }
        __syncthreads();
        if (ll < 3) {
            const int l = lg * 4 + ll + 1;
            #pragma unroll
            for (int q = 0; q < 4; q++) {
                int f = q * 256 + tid;
                int r = f >> 4, b4 = f & 15;
                abuf[q] = *(const uint4*)(g_t + ((size_t)l * 64 + r) * 16384
                                              + b0 + b4 * 4);
                wbuf[q] = *(const float4*)(g_Lq + (size_t)l * 4096 + f * 4);
            }
        }

        float acc[2][2][4] = {};
        #pragma unroll
        for (int kk = 0; kk < 4; kk++) {
            unsigned ah[2][4], al[2][4];
            #pragma unroll
            for (int mt = 0; mt < 2; mt++) {       // A via ldmatrix.trans
                unsigned row = kk * 16 + (lane & 7) + ((lane >> 4) << 3);
                unsigned cb = (M0 + mt * 16 + (((lane >> 3) & 1) << 3)) * 2;
                unsigned ph = SWZ(row * 128 + cb);
                LDSM4T(ah[mt][0], ah[mt][1], ah[mt][2], ah[mt][3], sb + S2_ATH + ph);
                LDSM4T(al[mt][0], al[mt][1], al[mt][2], al[mt][3], sb + S2_ATL + ph);
            }
            unsigned bh[4], bl[4];
            {
                unsigned row = N0 + (lane & 7) + ((lane >> 4) << 3);
                unsigned ph = SWZ(row * 128 + kk * 32 + (((lane >> 3) & 1) << 4));
                LDSM4(bh[0], bh[1], bh[2], bh[3], sb + S2_BH + ph);
                LDSM4(bl[0], bl[1], bl[2], bl[3], sb + S2_BL + ph);
            }
            #pragma unroll
            for (int mt = 0; mt < 2; mt++) {
                MMA(acc[mt][0], ah[mt], bh[0], bh[1]);
                MMA(acc[mt][0], al[mt], bh[0], bh[1]);
                MMA(acc[mt][0], ah[mt], bl[0], bl[1]);
                MMA(acc[mt][1], ah[mt], bh[2], bh[3]);
                MMA(acc[mt][1], al[mt], bh[2], bh[3]);
                MMA(acc[mt][1], ah[mt], bl[2], bl[3]);
            }
        }

        // stash D[b][s] into os plane ll
        #pragma unroll
        for (int mt = 0; mt < 2; mt++)
            #pragma unroll
            for (int nt = 0; nt < 2; nt++) {
                float* p = os + ll * 4224 + (M0 + mt * 16 + g) * 66
                              + N0 + nt * 8 + t2;
                *(float2*)p = make_float2(acc[mt][nt][0], acc[mt][nt][1]);
                *(float2*)(p + 8 * 66) = make_float2(acc[mt][nt][2], acc[mt][nt][3]);
            }
        __syncthreads();    // protects At/B refill AND os completeness
    }

    // gather 4 l's per (b,s) -> one float4 (16B granule)
    for (int e = tid; e < 4096; e += 256) {
        int b = e >> 6, s = e & 63;
        int idx = b * 66 + s;
        float4 v = make_float4(os[idx], os[4224 + idx],
                               os[8448 + idx], os[12672 + idx]);
        *(float4*)(y + (b0 + b) * 4096 + s * 64 + lg * 4) = v;
    }
}

// ---------------------------------------------------------------------------
extern "C" void kernel_launch(void* const* d_in, const int* in_sizes, int n_in,
                              void* d_out, int out_size) {
    const float* x = (const float*)d_in[0];
    const float* L = (const float*)d_in[1];
    const float* R = (const float*)d_in[2];
    float* y = (float*)d_out;

    cudaFuncSetAttribute(stage1_kernel,
                         cudaFuncAttributeMaxDynamicSharedMemorySize, S1_SMEM);
    cudaFuncSetAttribute(stage2_kernel,
                         cudaFuncAttributeMaxDynamicSharedMemorySize, S2_SMEM);

    cayley_kernel<<<128, 32>>>(L, R);
    stage1_kernel<<<dim3(64, 128), 256, S1_SMEM>>>(x);
    stage2_kernel<<<dim3(16, 256), 256, S2_SMEM>>>(y);
}

// round 7
// speedup vs baseline: 3.3043x; 1.0456x over previous
#include <cuda_runtime.h>
#include <cuda_fp16.h>

// ---------------------------------------------------------------------------
// GSOrthogonal round 7: fp16 split, f32-acc main term + f16-acc correction
// terms (hoping f16-acc HMMA is double-rate). Scale-free in-place GJ cayley.
//  stage1: g_t[l][r][b] = sum_p Rq[r][l][p] x[b][r*64+p]  (packed fp16 hi/lo)
//  stage2: y[b][s*64+l] = sum_r Lq[l][s][r] t[l][r][b]
// ---------------------------------------------------------------------------

__device__ unsigned g_Lq[64 * 64 * 64];          // packed fp16 hi | lo<<16
__device__ unsigned g_Rq[64 * 64 * 64];
__device__ unsigned g_t[(size_t)4096 * 16384];   // [l][r][b], hi | lo<<16

__device__ __forceinline__ unsigned smem_u32(const void* p) {
    unsigned a;
    asm("{ .reg .u64 t; cvta.to.shared.u64 t, %1; cvt.u32.u64 %0, t; }"
        : "=r"(a) : "l"(p));
    return a;
}

#define SWZ(o) ((o) ^ (((o) >> 3) & 0x70u))

#define LDSM4(r0, r1, r2, r3, addr)                                           \
    asm volatile("ldmatrix.sync.aligned.m8n8.x4.shared.b16 {%0,%1,%2,%3},[%4];" \
        : "=r"(r0), "=r"(r1), "=r"(r2), "=r"(r3) : "r"(addr))
#define LDSM4T(r0, r1, r2, r3, addr)                                          \
    asm volatile("ldmatrix.sync.aligned.m8n8.x4.trans.shared.b16 {%0,%1,%2,%3},[%4];" \
        : "=r"(r0), "=r"(r1), "=r"(r2), "=r"(r3) : "r"(addr))
// f32-accumulate fp16 MMA (main term)
#define MMAF(d, a, b0, b1)                                                    \
    asm volatile("mma.sync.aligned.m16n8k16.row.col.f32.f16.f16.f32 "         \
        "{%0,%1,%2,%3},{%4,%5,%6,%7},{%8,%9},{%0,%1,%2,%3};"                  \
        : "+f"((d)[0]), "+f"((d)[1]), "+f"((d)[2]), "+f"((d)[3])              \
        : "r"((a)[0]), "r"((a)[1]), "r"((a)[2]), "r"((a)[3]), "r"(b0), "r"(b1))
// f16-accumulate fp16 MMA (correction terms)
#define MMAH(d, a, b0, b1)                                                    \
    asm volatile("mma.sync.aligned.m16n8k16.row.col.f16.f16.f16.f16 "         \
        "{%0,%1},{%2,%3,%4,%5},{%6,%7},{%0,%1};"                              \
        : "+r"((d)[0]), "+r"((d)[1])                                          \
        : "r"((a)[0]), "r"((a)[1]), "r"((a)[2]), "r"((a)[3]), "r"(b0), "r"(b1))

__device__ __forceinline__ unsigned pack2h(__half a, __half b) {
    return (unsigned)__half_as_ushort(a) | ((unsigned)__half_as_ushort(b) << 16);
}
// float -> (hi fp16 | lo fp16 << 16)
__device__ __forceinline__ unsigned packh(float v) {
    __half h = __float2half_rn(v);
    __half l = __float2half_rn(v - __half2float(h));
    return pack2h(h, l);
}
// split float4 into fp16 hi/lo quads -> two 8B STS
__device__ __forceinline__ void split_sts(char* bh, char* bl, unsigned off,
                                          float4 v) {
    __half hx = __float2half_rn(v.x), hy = __float2half_rn(v.y);
    __half hz = __float2half_rn(v.z), hw = __float2half_rn(v.w);
    __half lx = __float2half_rn(v.x - __half2float(hx));
    __half ly = __float2half_rn(v.y - __half2float(hy));
    __half lz = __float2half_rn(v.z - __half2float(hz));
    __half lw = __float2half_rn(v.w - __half2float(hw));
    unsigned sw = SWZ(off);
    *(uint2*)(bh + sw) = make_uint2(pack2h(hx, hy), pack2h(hz, hw));
    *(uint2*)(bl + sw) = make_uint2(pack2h(lx, ly), pack2h(lz, lw));
}
// unpack 4 packed (hi|lo<<16) elements -> hi/lo quads
__device__ __forceinline__ void unpack_sts(char* bh, char* bl, unsigned off,
                                           uint4 u) {
    unsigned sw = SWZ(off);
    *(uint2*)(bh + sw) = make_uint2((u.x & 0xffffu) | (u.y << 16),
                                    (u.z & 0xffffu) | (u.w << 16));
    *(uint2*)(bl + sw) = make_uint2((u.x >> 16) | (u.y & 0xffff0000u),
                                    (u.z >> 16) | (u.w & 0xffff0000u));
}

// ---------------- Cayley: scale-free in-place GJ inverse of C = I + S -------
// Q = 2*(C^{-1})^T - I. Stored rows are never self-scaled; true_row =
// d_r * stored_row with d_r = 1/stored[r][r] at pivot time (kept in col 64).
// Row stride 68 floats: LDS.128 over 32 consecutive rows hits (r+c4)&7 per
// 8-lane phase -> conflict-free without XOR math.
#define CLD 68
__global__ __launch_bounds__(32) void cayley_kernel(
    const float* __restrict__ Lin, const float* __restrict__ Rin) {
    __shared__ float C[64 * CLD];
    __shared__ float scr[64 * 65];
    const int blk = blockIdx.x;
    const float* A = blk < 64 ? Lin + blk * 4096 : Rin + (blk - 64) * 4096;
    unsigned* Q = blk < 64 ? g_Lq + blk * 4096 : g_Rq + (blk - 64) * 4096;
    const int lane = threadIdx.x;
    const int r0 = lane, r1 = lane + 32;

    for (int e = lane; e < 4096; e += 32)
        scr[(e >> 6) * 65 + (e & 63)] = A[e];
    __syncwarp();
    for (int e = lane; e < 4096; e += 32) {
        int i = e >> 6, j = e & 63;
        C[i * CLD + j] = ((i == j) ? 1.0f : 0.0f)
                       + 0.5f * (scr[i * 65 + j] - scr[j * 65 + i]);
    }
    __syncwarp();

    for (int k = 0; k < 64; k++) {
        float piv = __fdividef(1.0f, C[k * CLD + k]);
        float f0 = C[r0 * CLD + k] * piv;
        float f1 = C[r1 * CLD + k] * piv;
        bool u0 = (r0 != k), u1 = (r1 != k);
        __syncwarp();
        const float4* p4 = (const float4*)(C + k * CLD);
        float4* m0 = (float4*)(C + r0 * CLD);
        float4* m1 = (float4*)(C + r1 * CLD);
        #pragma unroll
        for (int c4 = 0; c4 < 16; c4++) {
            float4 p = p4[c4];
            float4 a = m0[c4];
            a.x -= f0 * p.x; a.y -= f0 * p.y; a.z -= f0 * p.z; a.w -= f0 * p.w;
            if (u0) m0[c4] = a;
            float4 b = m1[c4];
            b.x -= f1 * p.x; b.y -= f1 * p.y; b.z -= f1 * p.z; b.w -= f1 * p.w;
            if (u1) m1[c4] = b;
        }
        // column-k fix (own lane, after vector writes -> program-order safe)
        if (u0) C[r0 * CLD + k] = -f0;
        else  { C[r0 * CLD + k] = 1.0f; C[r0 * CLD + 64] = piv; }
        if (u1) C[r1 * CLD + k] = -f1;
        else  { C[r1 * CLD + k] = 1.0f; C[r1 * CLD + 64] = piv; }
        __syncwarp();
    }

    // Q[a][b] = 2*d_b*stored[b][a] - delta(a,b); packed fp16 hi/lo
    for (int e = lane; e < 4096; e += 32) {
        int a = e >> 6, b = e & 63;
        float v = 2.0f * C[b * CLD + 64] * C[b * CLD + a] - (a == b ? 1.0f : 0.0f);
        Q[e] = packh(v);
    }
}

// ---------------- Stage 1: M=128(b) N=64(l) K=64(p) -------------------------
#define S1_AHI 0
#define S1_ALO 16384
#define S1_BHI 32768
#define S1_BLO 40960
#define S1_SMEM 49152

__global__ __launch_bounds__(256, 2) void stage1_kernel(const float* __restrict__ x) {
    extern __shared__ char sm[];
    const unsigned sb = smem_u32(sm);
    const int tid = threadIdx.x, wid = tid >> 5, lane = tid & 31;
    const int rblk = blockIdx.x;
    const long b0 = (long)blockIdx.y * 128;

    // A = x tile 128x64 (row=b, 128B fp16 rows), split on the fly
    #pragma unroll
    for (int q = 0; q < 8; q++) {
        int f = q * 256 + tid;
        int row = f >> 4, p4 = f & 15;
        float4 v = *(const float4*)(x + (b0 + row) * 4096 + rblk * 64 + p4 * 4);
        split_sts(sm + S1_AHI, sm + S1_ALO, (unsigned)(row * 128 + p4 * 8), v);
    }
    // B = Rq[rblk] 64x64, pre-packed -> unpack
    #pragma unroll
    for (int q = 0; q < 4; q++) {
        int f = q * 256 + tid;
        int row = f >> 4, p4 = f & 15;
        uint4 u = *(const uint4*)(g_Rq + (size_t)rblk * 4096 + row * 64 + p4 * 4);
        unpack_sts(sm + S1_BHI, sm + S1_BLO, (unsigned)(row * 128 + p4 * 8), u);
    }
    __syncthreads();

    const int wm = wid & 3, wn = wid >> 2;
    const int M0 = wm * 32, N0 = wn * 32;
    float acc[2][4][4] = {};
    unsigned acch[2][4][2] = {};

    #pragma unroll
    for (int kk = 0; kk < 4; kk++) {
        const unsigned kb = kk * 32;
        unsigned ah[2][4], al[2][4];
        #pragma unroll
        for (int mt = 0; mt < 2; mt++) {
            unsigned row = M0 + mt * 16 + (lane & 15);
            unsigned ph = SWZ(row * 128 + kb + ((lane >> 4) << 4));
            LDSM4(ah[mt][0], ah[mt][1], ah[mt][2], ah[mt][3], sb + S1_AHI + ph);
            LDSM4(al[mt][0], al[mt][1], al[mt][2], al[mt][3], sb + S1_ALO + ph);
        }
        unsigned bh[2][4], bl[2][4];
        #pragma unroll
        for (int nh = 0; nh < 2; nh++) {
            unsigned row = N0 + nh * 16 + (lane & 7) + ((lane >> 4) << 3);
            unsigned ph = SWZ(row * 128 + kb + (((lane >> 3) & 1) << 4));
            LDSM4(bh[nh][0], bh[nh][1], bh[nh][2], bh[nh][3], sb + S1_BHI + ph);
            LDSM4(bl[nh][0], bl[nh][1], bl[nh][2], bl[nh][3], sb + S1_BLO + ph);
        }
        #pragma unroll
        for (int mt = 0; mt < 2; mt++)
            #pragma unroll
            for (int nh = 0; nh < 2; nh++) {
                MMAF(acc[mt][nh * 2 + 0], ah[mt], bh[nh][0], bh[nh][1]);
                MMAH(acch[mt][nh * 2 + 0], al[mt], bh[nh][0], bh[nh][1]);
                MMAH(acch[mt][nh * 2 + 0], ah[mt], bl[nh][0], bl[nh][1]);
                MMAF(acc[mt][nh * 2 + 1], ah[mt], bh[nh][2], bh[nh][3]);
                MMAH(acch[mt][nh * 2 + 1], al[mt], bh[nh][2], bh[nh][3]);
                MMAH(acch[mt][nh * 2 + 1], ah[mt], bl[nh][2], bl[nh][3]);
            }
    }

    // epilogue: combine f32 + f16 acc, pack fp16 hi/lo, STG to g_t[l][r][b]
    const int g = lane >> 2, t2 = (lane & 3) << 1;
    #pragma unroll
    for (int mt = 0; mt < 2; mt++) {
        const long bb = b0 + M0 + mt * 16 + g;
        #pragma unroll
        for (int nt = 0; nt < 4; nt++) {
            float2 e0 = __half22float2(*(__half2*)&acch[mt][nt][0]);
            float2 e1 = __half22float2(*(__half2*)&acch[mt][nt][1]);
            int l0 = N0 + nt * 8 + t2;
            size_t base = ((size_t)l0 * 64 + rblk) * 16384;
            g_t[base + bb]               = packh(acc[mt][nt][0] + e0.x);
            g_t[base + 1048576 + bb]     = packh(acc[mt][nt][1] + e0.y);
            g_t[base + bb + 8]           = packh(acc[mt][nt][2] + e1.x);
            g_t[base + 1048576 + bb + 8] = packh(acc[mt][nt][3] + e1.y);
        }
    }
}

// ---------------- Stage 2: 4 l's per CTA, M=64(b) N=64(s) K=64(r) ----------
#define S2_ATH 0
#define S2_ATL 8192
#define S2_BH  16384
#define S2_BL  24576
#define S2_OS  32768
#define S2_SMEM (32768 + 4 * 64 * 66 * 4)     // 100352

__global__ __launch_bounds__(256, 2) void stage2_kernel(float* __restrict__ y) {
    extern __shared__ char sm[];
    const unsigned sb = smem_u32(sm);
    float* os = (float*)(sm + S2_OS);
    const int tid = threadIdx.x, wid = tid >> 5, lane = tid & 31;
    const int lg = blockIdx.x;                    // 0..15
    const long b0 = (long)blockIdx.y * 64;

    const int wm = wid & 1, wn = wid >> 1;        // warp tile m32 x n16
    const int M0 = wm * 32, N0 = wn * 16;
    const int g = lane >> 2, t2 = (lane & 3) << 1;

    uint4 abuf[4], wbuf[4];
    #pragma unroll
    for (int q = 0; q < 4; q++) {                 // prefetch ll=0
        int f = q * 256 + tid;
        int r = f >> 4, b4 = f & 15;
        abuf[q] = *(const uint4*)(g_t + ((size_t)(lg * 4) * 64 + r) * 16384
                                      + b0 + b4 * 4);
        wbuf[q] = *(const uint4*)(g_Lq + (size_t)(lg * 4) * 4096 + f * 4);
    }

    for (int ll = 0; ll < 4; ll++) {
        #pragma unroll
        for (int q = 0; q < 4; q++) {
            int f = q * 256 + tid;
            int r = f >> 4, b4 = f & 15;
            unpack_sts(sm + S2_ATH, sm + S2_ATL, (unsigned)(r * 128 + b4 * 8),
                       abuf[q]);                   // At[r][b]
            unpack_sts(sm + S2_BH, sm + S2_BL, (unsigned)(r * 128 + b4 * 8),
                       wbuf[q]);                   // W[s][r]
        }
        __syncthreads();
        if (ll < 3) {
            const int l = lg * 4 + ll + 1;
            #pragma unroll
            for (int q = 0; q < 4; q++) {
                int f = q * 256 + tid;
                int r = f >> 4, b4 = f & 15;
                abuf[q] = *(const uint4*)(g_t + ((size_t)l * 64 + r) * 16384
                                              + b0 + b4 * 4);
                wbuf[q] = *(const uint4*)(g_Lq + (size_t)l * 4096 + f * 4);
            }
        }

        float acc[2][2][4] = {};
        unsigned acch[2][2][2] = {};
        #pragma unroll
        for (int kk = 0; kk < 4; kk++) {
            unsigned ah[2][4], al[2][4];
            #pragma unroll
            for (int mt = 0; mt < 2; mt++) {       // A via ldmatrix.trans
                unsigned row = kk * 16 + (lane & 7) + ((lane >> 4) << 3);
                unsigned cb = (M0 + mt * 16 + (((lane >> 3) & 1) << 3)) * 2;
                unsigned ph = SWZ(row * 128 + cb);
                LDSM4T(ah[mt][0], ah[mt][1], ah[mt][2], ah[mt][3], sb + S2_ATH + ph);
                LDSM4T(al[mt][0], al[mt][1], al[mt][2], al[mt][3], sb + S2_ATL + ph);
            }
            unsigned bh[4], bl[4];
            {
                unsigned row = N0 + (lane & 7) + ((lane >> 4) << 3);
                unsigned ph = SWZ(row * 128 + kk * 32 + (((lane >> 3) & 1) << 4));
                LDSM4(bh[0], bh[1], bh[2], bh[3], sb + S2_BH + ph);
                LDSM4(bl[0], bl[1], bl[2], bl[3], sb + S2_BL + ph);
            }
            #pragma unroll
            for (int mt = 0; mt < 2; mt++) {
                MMAF(acc[mt][0], ah[mt], bh[0], bh[1]);
                MMAH(acch[mt][0], al[mt], bh[0], bh[1]);
                MMAH(acch[mt][0], ah[mt], bl[0], bl[1]);
                MMAF(acc[mt][1], ah[mt], bh[2], bh[3]);
                MMAH(acch[mt][1], al[mt], bh[2], bh[3]);
                MMAH(acch[mt][1], ah[mt], bl[2], bl[3]);
            }
        }

        // stash D[b][s] into os plane ll (f32 + f16 correction)
        #pragma unroll
        for (int mt = 0; mt < 2; mt++)
            #pragma unroll
            for (int nt = 0; nt < 2; nt++) {
                float2 e0 = __half22float2(*(__half2*)&acch[mt][nt][0]);
                float2 e1 = __half22float2(*(__half2*)&acch[mt][nt][1]);
                float* p = os + ll * 4224 + (M0 + mt * 16 + g) * 66
                              + N0 + nt * 8 + t2;
                *(float2*)p = make_float2(acc[mt][nt][0] + e0.x,
                                          acc[mt][nt][1] + e0.y);
                *(float2*)(p + 8 * 66) = make_float2(acc[mt][nt][2] + e1.x,
                                                     acc[mt][nt][3] + e1.y);
            }
        __syncthreads();
    }

    // gather 4 l's per (b,s) -> one float4
    for (int e = tid; e < 4096; e += 256) {
        int b = e >> 6, s = e & 63;
        int idx = b * 66 + s;
        float4 v = make_float4(os[idx], os[4224 + idx],
                               os[8448 + idx], os[12672 + idx]);
        *(float4*)(y + (b0 + b) * 4096 + s * 64 + lg * 4) = v;
    }
}

// ---------------------------------------------------------------------------
extern "C" void kernel_launch(void* const* d_in, const int* in_sizes, int n_in,
                              void* d_out, int out_size) {
    const float* x = (const float*)d_in[0];
    const float* L = (const float*)d_in[1];
    const float* R = (const float*)d_in[2];
    float* y = (float*)d_out;

    cudaFuncSetAttribute(stage1_kernel,
                         cudaFuncAttributeMaxDynamicSharedMemorySize, S1_SMEM);
    cudaFuncSetAttribute(stage2_kernel,
                         cudaFuncAttributeMaxDynamicSharedMemorySize, S2_SMEM);

    cayley_kernel<<<128, 32>>>(L, R);
    stage1_kernel<<<dim3(64, 128), 256, S1_SMEM>>>(x);
    stage2_kernel<<<dim3(16, 256), 256, S2_SMEM>>>(y);
}

// round 8
// speedup vs baseline: 3.4139x; 1.0332x over previous
#include <cuda_runtime.h>
#include <cuda_fp16.h>

// ---------------------------------------------------------------------------
// GSOrthogonal round 8: 2-term fp16 split (x/t exact as hi+lo, W single fp16;
// terms: ah*Wh + al*Wh). MMA count 2/3 of round 7. Cayley: 8 matrices/CTA
// for cross-warp latency hiding.
//  stage1: g_t[l][r][b] = sum_p Rq[r][l][p] x[b][r*64+p]  (packed fp16 hi/lo)
//  stage2: y[b][s*64+l] = sum_r Lq[l][s][r] t[l][r][b]
// ---------------------------------------------------------------------------

__device__ __half g_Lq[64 * 64 * 64];            // single fp16 weights
__device__ __half g_Rq[64 * 64 * 64];
__device__ unsigned g_t[(size_t)4096 * 16384];   // [l][r][b], hi | lo<<16

__device__ __forceinline__ unsigned smem_u32(const void* p) {
    unsigned a;
    asm("{ .reg .u64 t; cvta.to.shared.u64 t, %1; cvt.u32.u64 %0, t; }"
        : "=r"(a) : "l"(p));
    return a;
}

#define SWZ(o) ((o) ^ (((o) >> 3) & 0x70u))

#define LDSM4(r0, r1, r2, r3, addr)                                           \
    asm volatile("ldmatrix.sync.aligned.m8n8.x4.shared.b16 {%0,%1,%2,%3},[%4];" \
        : "=r"(r0), "=r"(r1), "=r"(r2), "=r"(r3) : "r"(addr))
#define LDSM4T(r0, r1, r2, r3, addr)                                          \
    asm volatile("ldmatrix.sync.aligned.m8n8.x4.trans.shared.b16 {%0,%1,%2,%3},[%4];" \
        : "=r"(r0), "=r"(r1), "=r"(r2), "=r"(r3) : "r"(addr))
#define MMAF(d, a, b0, b1)                                                    \
    asm volatile("mma.sync.aligned.m16n8k16.row.col.f32.f16.f16.f32 "         \
        "{%0,%1,%2,%3},{%4,%5,%6,%7},{%8,%9},{%0,%1,%2,%3};"                  \
        : "+f"((d)[0]), "+f"((d)[1]), "+f"((d)[2]), "+f"((d)[3])              \
        : "r"((a)[0]), "r"((a)[1]), "r"((a)[2]), "r"((a)[3]), "r"(b0), "r"(b1))

__device__ __forceinline__ unsigned pack2h(__half a, __half b) {
    return (unsigned)__half_as_ushort(a) | ((unsigned)__half_as_ushort(b) << 16);
}
__device__ __forceinline__ unsigned packh(float v) {
    __half h = __float2half_rn(v);
    __half l = __float2half_rn(v - __half2float(h));
    return pack2h(h, l);
}
// split float4 into fp16 hi/lo quads -> two 8B STS
__device__ __forceinline__ void split_sts(char* bh, char* bl, unsigned off,
                                          float4 v) {
    __half hx = __float2half_rn(v.x), hy = __float2half_rn(v.y);
    __half hz = __float2half_rn(v.z), hw = __float2half_rn(v.w);
    __half lx = __float2half_rn(v.x - __half2float(hx));
    __half ly = __float2half_rn(v.y - __half2float(hy));
    __half lz = __float2half_rn(v.z - __half2float(hz));
    __half lw = __float2half_rn(v.w - __half2float(hw));
    unsigned sw = SWZ(off);
    *(uint2*)(bh + sw) = make_uint2(pack2h(hx, hy), pack2h(hz, hw));
    *(uint2*)(bl + sw) = make_uint2(pack2h(lx, ly), pack2h(lz, lw));
}
// unpack 4 packed (hi|lo<<16) elements -> hi/lo quads
__device__ __forceinline__ void unpack_sts(char* bh, char* bl, unsigned off,
                                           uint4 u) {
    unsigned sw = SWZ(off);
    *(uint2*)(bh + sw) = make_uint2((u.x & 0xffffu) | (u.y << 16),
                                    (u.z & 0xffffu) | (u.w << 16));
    *(uint2*)(bl + sw) = make_uint2((u.x >> 16) | (u.y & 0xffff0000u),
                                    (u.z >> 16) | (u.w & 0xffff0000u));
}

// ---------------- Cayley: scale-free GJ inverse, 8 matrices per CTA ---------
// Q = 2*(C^{-1})^T - I with C = I + S. 1 warp per matrix, 8 warps per CTA
// (2 warps/SMSP -> LDS latency hiding). Row stride 68 floats: conflict-free.
#define CLD 68
__global__ __launch_bounds__(256) void cayley_kernel(
    const float* __restrict__ Lin, const float* __restrict__ Rin) {
    extern __shared__ float Call[];               // 8 planes of 64*CLD
    const int wid = threadIdx.x >> 5, lane = threadIdx.x & 31;
    const int blk = blockIdx.x * 8 + wid;         // 0..127
    const float* A = blk < 64 ? Lin + blk * 4096 : Rin + (blk - 64) * 4096;
    __half* Q = blk < 64 ? g_Lq + blk * 4096 : g_Rq + (blk - 64) * 4096;
    float* C = Call + wid * 64 * CLD;
    const int r0 = lane, r1 = lane + 32;

    // C = I + S  (A^T reads mostly L1-hit; matrix is 16KB)
    for (int e = lane; e < 4096; e += 32) {
        int i = e >> 6, j = e & 63;
        C[i * CLD + j] = ((i == j) ? 1.0f : 0.0f)
                       + 0.5f * (A[i * 64 + j] - A[j * 64 + i]);
    }
    __syncwarp();

    for (int k = 0; k < 64; k++) {
        float piv = __fdividef(1.0f, C[k * CLD + k]);
        float f0 = C[r0 * CLD + k] * piv;
        float f1 = C[r1 * CLD + k] * piv;
        bool u0 = (r0 != k), u1 = (r1 != k);
        __syncwarp();
        const float4* p4 = (const float4*)(C + k * CLD);
        float4* m0 = (float4*)(C + r0 * CLD);
        float4* m1 = (float4*)(C + r1 * CLD);
        #pragma unroll
        for (int c4 = 0; c4 < 16; c4++) {
            float4 p = p4[c4];
            float4 a = m0[c4];
            a.x -= f0 * p.x; a.y -= f0 * p.y; a.z -= f0 * p.z; a.w -= f0 * p.w;
            if (u0) m0[c4] = a;
            float4 b = m1[c4];
            b.x -= f1 * p.x; b.y -= f1 * p.y; b.z -= f1 * p.z; b.w -= f1 * p.w;
            if (u1) m1[c4] = b;
        }
        if (u0) C[r0 * CLD + k] = -f0;
        else  { C[r0 * CLD + k] = 1.0f; C[r0 * CLD + 64] = piv; }
        if (u1) C[r1 * CLD + k] = -f1;
        else  { C[r1 * CLD + k] = 1.0f; C[r1 * CLD + 64] = piv; }
        __syncwarp();
    }

    // Q[a][b] = 2*d_b*stored[b][a] - delta(a,b), emitted as fp16
    for (int e = lane; e < 4096; e += 32) {
        int a = e >> 6, b = e & 63;
        float v = 2.0f * C[b * CLD + 64] * C[b * CLD + a] - (a == b ? 1.0f : 0.0f);
        Q[e] = __float2half_rn(v);
    }
}

// ---------------- Stage 1: M=128(b) N=64(l) K=64(p) -------------------------
#define S1_AHI 0
#define S1_ALO 16384
#define S1_BH  32768
#define S1_SMEM 40960

__global__ __launch_bounds__(256, 2) void stage1_kernel(const float* __restrict__ x) {
    extern __shared__ char sm[];
    const unsigned sb = smem_u32(sm);
    const int tid = threadIdx.x, wid = tid >> 5, lane = tid & 31;
    const int rblk = blockIdx.x;
    const long b0 = (long)blockIdx.y * 128;

    // A = x tile 128x64 (row=b), split to fp16 hi/lo
    #pragma unroll
    for (int q = 0; q < 8; q++) {
        int f = q * 256 + tid;
        int row = f >> 4, p4 = f & 15;
        float4 v = *(const float4*)(x + (b0 + row) * 4096 + rblk * 64 + p4 * 4);
        split_sts(sm + S1_AHI, sm + S1_ALO, (unsigned)(row * 128 + p4 * 8), v);
    }
    // B = Rq[rblk] 64x64 fp16 (single digit)
    #pragma unroll
    for (int q = 0; q < 4; q++) {
        int f = q * 256 + tid;
        int row = f >> 4, c4 = f & 15;
        uint2 u = *(const uint2*)((const __half*)g_Rq + (size_t)rblk * 4096 + f * 4);
        *(uint2*)(sm + S1_BH + SWZ((unsigned)(row * 128 + c4 * 8))) = u;
    }
    __syncthreads();

    const int wm = wid & 3, wn = wid >> 2;
    const int M0 = wm * 32, N0 = wn * 32;
    float acc[2][4][4] = {};

    #pragma unroll
    for (int kk = 0; kk < 4; kk++) {
        const unsigned kb = kk * 32;
        unsigned ah[2][4], al[2][4];
        #pragma unroll
        for (int mt = 0; mt < 2; mt++) {
            unsigned row = M0 + mt * 16 + (lane & 15);
            unsigned ph = SWZ(row * 128 + kb + ((lane >> 4) << 4));
            LDSM4(ah[mt][0], ah[mt][1], ah[mt][2], ah[mt][3], sb + S1_AHI + ph);
            LDSM4(al[mt][0], al[mt][1], al[mt][2], al[mt][3], sb + S1_ALO + ph);
        }
        unsigned bh[2][4];
        #pragma unroll
        for (int nh = 0; nh < 2; nh++) {
            unsigned row = N0 + nh * 16 + (lane & 7) + ((lane >> 4) << 3);
            unsigned ph = SWZ(row * 128 + kb + (((lane >> 3) & 1) << 4));
            LDSM4(bh[nh][0], bh[nh][1], bh[nh][2], bh[nh][3], sb + S1_BH + ph);
        }
        #pragma unroll
        for (int mt = 0; mt < 2; mt++)
            #pragma unroll
            for (int nh = 0; nh < 2; nh++) {
                MMAF(acc[mt][nh * 2 + 0], ah[mt], bh[nh][0], bh[nh][1]);
                MMAF(acc[mt][nh * 2 + 0], al[mt], bh[nh][0], bh[nh][1]);
                MMAF(acc[mt][nh * 2 + 1], ah[mt], bh[nh][2], bh[nh][3]);
                MMAF(acc[mt][nh * 2 + 1], al[mt], bh[nh][2], bh[nh][3]);
            }
    }

    // epilogue: pack fp32 -> fp16 hi/lo u32, STG to g_t[l][r][b]
    const int g = lane >> 2, t2 = (lane & 3) << 1;
    #pragma unroll
    for (int mt = 0; mt < 2; mt++) {
        const long bb = b0 + M0 + mt * 16 + g;
        #pragma unroll
        for (int nt = 0; nt < 4; nt++) {
            int l0 = N0 + nt * 8 + t2;
            size_t base = ((size_t)l0 * 64 + rblk) * 16384;
            g_t[base + bb]               = packh(acc[mt][nt][0]);
            g_t[base + 1048576 + bb]     = packh(acc[mt][nt][1]);   // l0+1
            g_t[base + bb + 8]           = packh(acc[mt][nt][2]);
            g_t[base + 1048576 + bb + 8] = packh(acc[mt][nt][3]);
        }
    }
}

// ---------------- Stage 2: 4 l's per CTA, M=64(b) N=64(s) K=64(r) ----------
#define S2_ATH 0
#define S2_ATL 8192
#define S2_BH  16384
#define S2_OS  24576
#define S2_SMEM (24576 + 4 * 64 * 66 * 4)     // 92160

__global__ __launch_bounds__(256, 2) void stage2_kernel(float* __restrict__ y) {
    extern __shared__ char sm[];
    const unsigned sb = smem_u32(sm);
    float* os = (float*)(sm + S2_OS);
    const int tid = threadIdx.x, wid = tid >> 5, lane = tid & 31;
    const int lg = blockIdx.x;                    // 0..15
    const long b0 = (long)blockIdx.y * 64;

    const int wm = wid & 1, wn = wid >> 1;        // warp tile m32 x n16
    const int M0 = wm * 32, N0 = wn * 16;
    const int g = lane >> 2, t2 = (lane & 3) << 1;

    uint4 abuf[4];
    uint2 wbuf[4];
    #pragma unroll
    for (int q = 0; q < 4; q++) {                 // prefetch ll=0
        int f = q * 256 + tid;
        int r = f >> 4, b4 = f & 15;
        abuf[q] = *(const uint4*)(g_t + ((size_t)(lg * 4) * 64 + r) * 16384
                                      + b0 + b4 * 4);
        wbuf[q] = *(const uint2*)((const __half*)g_Lq + (size_t)(lg * 4) * 4096
                                  + f * 4);
    }

    for (int ll = 0; ll < 4; ll++) {
        #pragma unroll
        for (int q = 0; q < 4; q++) {
            int f = q * 256 + tid;
            int r = f >> 4, b4 = f & 15;
            unpack_sts(sm + S2_ATH, sm + S2_ATL, (unsigned)(r * 128 + b4 * 8),
                       abuf[q]);                   // At[r][b]
            *(uint2*)(sm + S2_BH + SWZ((unsigned)(r * 128 + b4 * 8))) = wbuf[q];
        }
        __syncthreads();
        if (ll < 3) {
            const int l = lg * 4 + ll + 1;
            #pragma unroll
            for (int q = 0; q < 4; q++) {
                int f = q * 256 + tid;
                int r = f >> 4, b4 = f & 15;
                abuf[q] = *(const uint4*)(g_t + ((size_t)l * 64 + r) * 16384
                                              + b0 + b4 * 4);
                wbuf[q] = *(const uint2*)((const __half*)g_Lq + (size_t)l * 4096
                                          + f * 4);
            }
        }

        float acc[2][2][4] = {};
        #pragma unroll
        for (int kk = 0; kk < 4; kk++) {
            unsigned ah[2][4], al[2][4];
            #pragma unroll
            for (int mt = 0; mt < 2; mt++) {       // A via ldmatrix.trans
                unsigned row = kk * 16 + (lane & 7) + ((lane >> 4) << 3);
                unsigned cb = (M0 + mt * 16 + (((lane >> 3) & 1) << 3)) * 2;
                unsigned ph = SWZ(row * 128 + cb);
                LDSM4T(ah[mt][0], ah[mt][1], ah[mt][2], ah[mt][3], sb + S2_ATH + ph);
                LDSM4T(al[mt][0], al[mt][1], al[mt][2], al[mt][3], sb + S2_ATL + ph);
            }
            unsigned bh[4];
            {
                unsigned row = N0 + (lane & 7) + ((lane >> 4) << 3);
                unsigned ph = SWZ(row * 128 + kk * 32 + (((lane >> 3) & 1) << 4));
                LDSM4(bh[0], bh[1], bh[2], bh[3], sb + S2_BH + ph);
            }
            #pragma unroll
            for (int mt = 0; mt < 2; mt++) {
                MMAF(acc[mt][0], ah[mt], bh[0], bh[1]);
                MMAF(acc[mt][0], al[mt], bh[0], bh[1]);
                MMAF(acc[mt][1], ah[mt], bh[2], bh[3]);
                MMAF(acc[mt][1], al[mt], bh[2], bh[3]);
            }
        }

        // stash D[b][s] into os plane ll
        #pragma unroll
        for (int mt = 0; mt < 2; mt++)
            #pragma unroll
            for (int nt = 0; nt < 2; nt++) {
                float* p = os + ll * 4224 + (M0 + mt * 16 + g) * 66
                              + N0 + nt * 8 + t2;
                *(float2*)p = make_float2(acc[mt][nt][0], acc[mt][nt][1]);
                *(float2*)(p + 8 * 66) = make_float2(acc[mt][nt][2], acc[mt][nt][3]);
            }
        __syncthreads();
    }

    // gather 4 l's per (b,s) -> one float4
    for (int e = tid; e < 4096; e += 256) {
        int b = e >> 6, s = e & 63;
        int idx = b * 66 + s;
        float4 v = make_float4(os[idx], os[4224 + idx],
                               os[8448 + idx], os[12672 + idx]);
        *(float4*)(y + (b0 + b) * 4096 + s * 64 + lg * 4) = v;
    }
}

// ---------------------------------------------------------------------------
extern "C" void kernel_launch(void* const* d_in, const int* in_sizes, int n_in,
                              void* d_out, int out_size) {
    const float* x = (const float*)d_in[0];
    const float* L = (const float*)d_in[1];
    const float* R = (const float*)d_in[2];
    float* y = (float*)d_out;

    const int cay_smem = 8 * 64 * CLD * 4;        // 139264
    cudaFuncSetAttribute(cayley_kernel,
                         cudaFuncAttributeMaxDynamicSharedMemorySize, cay_smem);
    cudaFuncSetAttribute(stage1_kernel,
                         cudaFuncAttributeMaxDynamicSharedMemorySize, S1_SMEM);
    cudaFuncSetAttribute(stage2_kernel,
                         cudaFuncAttributeMaxDynamicSharedMemorySize, S2_SMEM);

    cayley_kernel<<<16, 256, cay_smem>>>(L, R);
    stage1_kernel<<<dim3(64, 128), 256, S1_SMEM>>>(x);
    stage2_kernel<<<dim3(16, 256), 256, S2_SMEM>>>(y);
}

// round 9
// speedup vs baseline: 3.9810x; 1.1661x over previous
#include <cuda_runtime.h>
#include <cuda_fp16.h>

// ---------------------------------------------------------------------------
// GSOrthogonal round 9: round-8 stages (unchanged) + register-blocked cayley
// (1 warp/CTA x 128 CTAs; 8-chunk batched LDS halves to hide LDS latency).
//  stage1: g_t[l][r][b] = sum_p Rq[r][l][p] x[b][r*64+p]  (packed fp16 hi/lo)
//  stage2: y[b][s*64+l] = sum_r Lq[l][s][r] t[l][r][b]
//  2-term fp16 split: ah*Wh + al*Wh, f32 accumulate.
// ---------------------------------------------------------------------------

__device__ __half g_Lq[64 * 64 * 64];            // single fp16 weights
__device__ __half g_Rq[64 * 64 * 64];
__device__ unsigned g_t[(size_t)4096 * 16384];   // [l][r][b], hi | lo<<16

__device__ __forceinline__ unsigned smem_u32(const void* p) {
    unsigned a;
    asm("{ .reg .u64 t; cvta.to.shared.u64 t, %1; cvt.u32.u64 %0, t; }"
        : "=r"(a) : "l"(p));
    return a;
}

#define SWZ(o) ((o) ^ (((o) >> 3) & 0x70u))

#define LDSM4(r0, r1, r2, r3, addr)                                           \
    asm volatile("ldmatrix.sync.aligned.m8n8.x4.shared.b16 {%0,%1,%2,%3},[%4];" \
        : "=r"(r0), "=r"(r1), "=r"(r2), "=r"(r3) : "r"(addr))
#define LDSM4T(r0, r1, r2, r3, addr)                                          \
    asm volatile("ldmatrix.sync.aligned.m8n8.x4.trans.shared.b16 {%0,%1,%2,%3},[%4];" \
        : "=r"(r0), "=r"(r1), "=r"(r2), "=r"(r3) : "r"(addr))
#define MMAF(d, a, b0, b1)                                                    \
    asm volatile("mma.sync.aligned.m16n8k16.row.col.f32.f16.f16.f32 "         \
        "{%0,%1,%2,%3},{%4,%5,%6,%7},{%8,%9},{%0,%1,%2,%3};"                  \
        : "+f"((d)[0]), "+f"((d)[1]), "+f"((d)[2]), "+f"((d)[3])              \
        : "r"((a)[0]), "r"((a)[1]), "r"((a)[2]), "r"((a)[3]), "r"(b0), "r"(b1))

__device__ __forceinline__ unsigned pack2h(__half a, __half b) {
    return (unsigned)__half_as_ushort(a) | ((unsigned)__half_as_ushort(b) << 16);
}
__device__ __forceinline__ unsigned packh(float v) {
    __half h = __float2half_rn(v);
    __half l = __float2half_rn(v - __half2float(h));
    return pack2h(h, l);
}
__device__ __forceinline__ void split_sts(char* bh, char* bl, unsigned off,
                                          float4 v) {
    __half hx = __float2half_rn(v.x), hy = __float2half_rn(v.y);
    __half hz = __float2half_rn(v.z), hw = __float2half_rn(v.w);
    __half lx = __float2half_rn(v.x - __half2float(hx));
    __half ly = __float2half_rn(v.y - __half2float(hy));
    __half lz = __float2half_rn(v.z - __half2float(hz));
    __half lw = __float2half_rn(v.w - __half2float(hw));
    unsigned sw = SWZ(off);
    *(uint2*)(bh + sw) = make_uint2(pack2h(hx, hy), pack2h(hz, hw));
    *(uint2*)(bl + sw) = make_uint2(pack2h(lx, ly), pack2h(lz, lw));
}
__device__ __forceinline__ void unpack_sts(char* bh, char* bl, unsigned off,
                                           uint4 u) {
    unsigned sw = SWZ(off);
    *(uint2*)(bh + sw) = make_uint2((u.x & 0xffffu) | (u.y << 16),
                                    (u.z & 0xffffu) | (u.w << 16));
    *(uint2*)(bl + sw) = make_uint2((u.x >> 16) | (u.y & 0xffff0000u),
                                    (u.z >> 16) | (u.w & 0xffff0000u));
}

// ---------------- Cayley: scale-free GJ inverse, register-blocked -----------
// Q = 2*(C^{-1})^T - I with C = I + S. 1 warp per matrix, 128 CTAs (1/SM).
// Each iter processed in 2 halves of 8 float4 chunks: 24 batched LDS.128
// (pivot + r0 + r1), FFMA block, guarded batched STS -> one exposed LDS
// latency per half instead of per chunk.
#define CLD 68
__global__ __launch_bounds__(32) void cayley_kernel(
    const float* __restrict__ Lin, const float* __restrict__ Rin) {
    __shared__ float C[64 * CLD];
    const int blk = blockIdx.x;
    const float* A = blk < 64 ? Lin + blk * 4096 : Rin + (blk - 64) * 4096;
    __half* Q = blk < 64 ? g_Lq + blk * 4096 : g_Rq + (blk - 64) * 4096;
    const int lane = threadIdx.x;
    const int r0 = lane, r1 = lane + 32;

    for (int e = lane; e < 4096; e += 32) {
        int i = e >> 6, j = e & 63;
        C[i * CLD + j] = ((i == j) ? 1.0f : 0.0f)
                       + 0.5f * (A[i * 64 + j] - A[j * 64 + i]);
    }
    __syncwarp();

    for (int k = 0; k < 64; k++) {
        float piv = __fdividef(1.0f, C[k * CLD + k]);
        float f0 = C[r0 * CLD + k] * piv;
        float f1 = C[r1 * CLD + k] * piv;
        bool u0 = (r0 != k), u1 = (r1 != k);
        __syncwarp();
        #pragma unroll
        for (int h = 0; h < 2; h++) {
            const float4* p4 = (const float4*)(C + k * CLD) + h * 8;
            float4* m0 = (float4*)(C + r0 * CLD) + h * 8;
            float4* m1 = (float4*)(C + r1 * CLD) + h * 8;
            float4 p[8], a[8], b[8];
            #pragma unroll
            for (int c = 0; c < 8; c++) p[c] = p4[c];
            #pragma unroll
            for (int c = 0; c < 8; c++) a[c] = m0[c];
            #pragma unroll
            for (int c = 0; c < 8; c++) b[c] = m1[c];
            #pragma unroll
            for (int c = 0; c < 8; c++) {
                a[c].x -= f0 * p[c].x; a[c].y -= f0 * p[c].y;
                a[c].z -= f0 * p[c].z; a[c].w -= f0 * p[c].w;
                b[c].x -= f1 * p[c].x; b[c].y -= f1 * p[c].y;
                b[c].z -= f1 * p[c].z; b[c].w -= f1 * p[c].w;
            }
            if (u0) {
                #pragma unroll
                for (int c = 0; c < 8; c++) m0[c] = a[c];
            }
            if (u1) {
                #pragma unroll
                for (int c = 0; c < 8; c++) m1[c] = b[c];
            }
        }
        if (u0) C[r0 * CLD + k] = -f0;
        else  { C[r0 * CLD + k] = 1.0f; C[r0 * CLD + 64] = piv; }
        if (u1) C[r1 * CLD + k] = -f1;
        else  { C[r1 * CLD + k] = 1.0f; C[r1 * CLD + 64] = piv; }
        __syncwarp();
    }

    // Q[a][b] = 2*d_b*stored[b][a] - delta(a,b), emitted as fp16
    for (int e = lane; e < 4096; e += 32) {
        int a = e >> 6, b = e & 63;
        float v = 2.0f * C[b * CLD + 64] * C[b * CLD + a] - (a == b ? 1.0f : 0.0f);
        Q[e] = __float2half_rn(v);
    }
}

// ---------------- Stage 1: M=128(b) N=64(l) K=64(p) -------------------------
#define S1_AHI 0
#define S1_ALO 16384
#define S1_BH  32768
#define S1_SMEM 40960

__global__ __launch_bounds__(256, 2) void stage1_kernel(const float* __restrict__ x) {
    extern __shared__ char sm[];
    const unsigned sb = smem_u32(sm);
    const int tid = threadIdx.x, wid = tid >> 5, lane = tid & 31;
    const int rblk = blockIdx.x;
    const long b0 = (long)blockIdx.y * 128;

    #pragma unroll
    for (int q = 0; q < 8; q++) {
        int f = q * 256 + tid;
        int row = f >> 4, p4 = f & 15;
        float4 v = *(const float4*)(x + (b0 + row) * 4096 + rblk * 64 + p4 * 4);
        split_sts(sm + S1_AHI, sm + S1_ALO, (unsigned)(row * 128 + p4 * 8), v);
    }
    #pragma unroll
    for (int q = 0; q < 4; q++) {
        int f = q * 256 + tid;
        int row = f >> 4, c4 = f & 15;
        uint2 u = *(const uint2*)((const __half*)g_Rq + (size_t)rblk * 4096 + f * 4);
        *(uint2*)(sm + S1_BH + SWZ((unsigned)(row * 128 + c4 * 8))) = u;
    }
    __syncthreads();

    const int wm = wid & 3, wn = wid >> 2;
    const int M0 = wm * 32, N0 = wn * 32;
    float acc[2][4][4] = {};

    #pragma unroll
    for (int kk = 0; kk < 4; kk++) {
        const unsigned kb = kk * 32;
        unsigned ah[2][4], al[2][4];
        #pragma unroll
        for (int mt = 0; mt < 2; mt++) {
            unsigned row = M0 + mt * 16 + (lane & 15);
            unsigned ph = SWZ(row * 128 + kb + ((lane >> 4) << 4));
            LDSM4(ah[mt][0], ah[mt][1], ah[mt][2], ah[mt][3], sb + S1_AHI + ph);
            LDSM4(al[mt][0], al[mt][1], al[mt][2], al[mt][3], sb + S1_ALO + ph);
        }
        unsigned bh[2][4];
        #pragma unroll
        for (int nh = 0; nh < 2; nh++) {
            unsigned row = N0 + nh * 16 + (lane & 7) + ((lane >> 4) << 3);
            unsigned ph = SWZ(row * 128 + kb + (((lane >> 3) & 1) << 4));
            LDSM4(bh[nh][0], bh[nh][1], bh[nh][2], bh[nh][3], sb + S1_BH + ph);
        }
        #pragma unroll
        for (int mt = 0; mt < 2; mt++)
            #pragma unroll
            for (int nh = 0; nh < 2; nh++) {
                MMAF(acc[mt][nh * 2 + 0], ah[mt], bh[nh][0], bh[nh][1]);
                MMAF(acc[mt][nh * 2 + 0], al[mt], bh[nh][0], bh[nh][1]);
                MMAF(acc[mt][nh * 2 + 1], ah[mt], bh[nh][2], bh[nh][3]);
                MMAF(acc[mt][nh * 2 + 1], al[mt], bh[nh][2], bh[nh][3]);
            }
    }

    const int g = lane >> 2, t2 = (lane & 3) << 1;
    #pragma unroll
    for (int mt = 0; mt < 2; mt++) {
        const long bb = b0 + M0 + mt * 16 + g;
        #pragma unroll
        for (int nt = 0; nt < 4; nt++) {
            int l0 = N0 + nt * 8 + t2;
            size_t base = ((size_t)l0 * 64 + rblk) * 16384;
            g_t[base + bb]               = packh(acc[mt][nt][0]);
            g_t[base + 1048576 + bb]     = packh(acc[mt][nt][1]);   // l0+1
            g_t[base + bb + 8]           = packh(acc[mt][nt][2]);
            g_t[base + 1048576 + bb + 8] = packh(acc[mt][nt][3]);
        }
    }
}

// ---------------- Stage 2: 4 l's per CTA, M=64(b) N=64(s) K=64(r) ----------
#define S2_ATH 0
#define S2_ATL 8192
#define S2_BH  16384
#define S2_OS  24576
#define S2_SMEM (24576 + 4 * 64 * 66 * 4)     // 92160

__global__ __launch_bounds__(256, 2) void stage2_kernel(float* __restrict__ y) {
    extern __shared__ char sm[];
    const unsigned sb = smem_u32(sm);
    float* os = (float*)(sm + S2_OS);
    const int tid = threadIdx.x, wid = tid >> 5, lane = tid & 31;
    const int lg = blockIdx.x;                    // 0..15
    const long b0 = (long)blockIdx.y * 64;

    const int wm = wid & 1, wn = wid >> 1;
    const int M0 = wm * 32, N0 = wn * 16;
    const int g = lane >> 2, t2 = (lane & 3) << 1;

    uint4 abuf[4];
    uint2 wbuf[4];
    #pragma unroll
    for (int q = 0; q < 4; q++) {
        int f = q * 256 + tid;
        int r = f >> 4, b4 = f & 15;
        abuf[q] = *(const uint4*)(g_t + ((size_t)(lg * 4) * 64 + r) * 16384
                                      + b0 + b4 * 4);
        wbuf[q] = *(const uint2*)((const __half*)g_Lq + (size_t)(lg * 4) * 4096
                                  + f * 4);
    }

    for (int ll = 0; ll < 4; ll++) {
        #pragma unroll
        for (int q = 0; q < 4; q++) {
            int f = q * 256 + tid;
            int r = f >> 4, b4 = f & 15;
            unpack_sts(sm + S2_ATH, sm + S2_ATL, (unsigned)(r * 128 + b4 * 8),
                       abuf[q]);
            *(uint2*)(sm + S2_BH + SWZ((unsigned)(r * 128 + b4 * 8))) = wbuf[q];
        }
        __syncthreads();
        if (ll < 3) {
            const int l = lg * 4 + ll + 1;
            #pragma unroll
            for (int q = 0; q < 4; q++) {
                int f = q * 256 + tid;
                int r = f >> 4, b4 = f & 15;
                abuf[q] = *(const uint4*)(g_t + ((size_t)l * 64 + r) * 16384
                                              + b0 + b4 * 4);
                wbuf[q] = *(const uint2*)((const __half*)g_Lq + (size_t)l * 4096
                                          + f * 4);
            }
        }

        float acc[2][2][4] = {};
        #pragma unroll
        for (int kk = 0; kk < 4; kk++) {
            unsigned ah[2][4], al[2][4];
            #pragma unroll
            for (int mt = 0; mt < 2; mt++) {
                unsigned row = kk * 16 + (lane & 7) + ((lane >> 4) << 3);
                unsigned cb = (M0 + mt * 16 + (((lane >> 3) & 1) << 3)) * 2;
                unsigned ph = SWZ(row * 128 + cb);
                LDSM4T(ah[mt][0], ah[mt][1], ah[mt][2], ah[mt][3], sb + S2_ATH + ph);
                LDSM4T(al[mt][0], al[mt][1], al[mt][2], al[mt][3], sb + S2_ATL + ph);
            }
            unsigned bh[4];
            {
                unsigned row = N0 + (lane & 7) + ((lane >> 4) << 3);
                unsigned ph = SWZ(row * 128 + kk * 32 + (((lane >> 3) & 1) << 4));
                LDSM4(bh[0], bh[1], bh[2], bh[3], sb + S2_BH + ph);
            }
            #pragma unroll
            for (int mt = 0; mt < 2; mt++) {
                MMAF(acc[mt][0], ah[mt], bh[0], bh[1]);
                MMAF(acc[mt][0], al[mt], bh[0], bh[1]);
                MMAF(acc[mt][1], ah[mt], bh[2], bh[3]);
                MMAF(acc[mt][1], al[mt], bh[2], bh[3]);
            }
        }

        #pragma unroll
        for (int mt = 0; mt < 2; mt++)
            #pragma unroll
            for (int nt = 0; nt < 2; nt++) {
                float* p = os + ll * 4224 + (M0 + mt * 16 + g) * 66
                              + N0 + nt * 8 + t2;
                *(float2*)p = make_float2(acc[mt][nt][0], acc[mt][nt][1]);
                *(float2*)(p + 8 * 66) = make_float2(acc[mt][nt][2], acc[mt][nt][3]);
            }
        __syncthreads();
    }

    for (int e = tid; e < 4096; e += 256) {
        int b = e >> 6, s = e & 63;
        int idx = b * 66 + s;
        float4 v = make_float4(os[idx], os[4224 + idx],
                               os[8448 + idx], os[12672 + idx]);
        *(float4*)(y + (b0 + b) * 4096 + s * 64 + lg * 4) = v;
    }
}

// ---------------------------------------------------------------------------
extern "C" void kernel_launch(void* const* d_in, const int* in_sizes, int n_in,
                              void* d_out, int out_size) {
    const float* x = (const float*)d_in[0];
    const float* L = (const float*)d_in[1];
    const float* R = (const float*)d_in[2];
    float* y = (float*)d_out;

    cudaFuncSetAttribute(stage1_kernel,
                         cudaFuncAttributeMaxDynamicSharedMemorySize, S1_SMEM);
    cudaFuncSetAttribute(stage2_kernel,
                         cudaFuncAttributeMaxDynamicSharedMemorySize, S2_SMEM);

    cayley_kernel<<<128, 32>>>(L, R);
    stage1_kernel<<<dim3(64, 128), 256, S1_SMEM>>>(x);
    stage2_kernel<<<dim3(16, 256), 256, S2_SMEM>>>(y);
}

// round 10
// speedup vs baseline: 4.2060x; 1.0565x over previous
#include <cuda_runtime.h>
#include <cuda_fp16.h>

// ---------------------------------------------------------------------------
// GSOrthogonal round 10: drop t_lo digit. Stage1 = 2-term (x hi+lo, W fp16),
// t stored single fp16; stage2 = 1-term (t fp16, W fp16). MMA 25.8G total.
//  stage1: g_t[l][r][b] = sum_p Rq[r][l][p] x[b][r*64+p]   (fp16)
//  stage2: y[b][s*64+l] = sum_r Lq[l][s][r] t[l][r][b]
// ---------------------------------------------------------------------------

__device__ __half g_Lq[64 * 64 * 64];            // fp16 weights
__device__ __half g_Rq[64 * 64 * 64];
__device__ __half g_t[(size_t)4096 * 16384];     // [l][r][b] fp16

__device__ __forceinline__ unsigned smem_u32(const void* p) {
    unsigned a;
    asm("{ .reg .u64 t; cvta.to.shared.u64 t, %1; cvt.u32.u64 %0, t; }"
        : "=r"(a) : "l"(p));
    return a;
}

#define SWZ(o) ((o) ^ (((o) >> 3) & 0x70u))

#define LDSM4(r0, r1, r2, r3, addr)                                           \
    asm volatile("ldmatrix.sync.aligned.m8n8.x4.shared.b16 {%0,%1,%2,%3},[%4];" \
        : "=r"(r0), "=r"(r1), "=r"(r2), "=r"(r3) : "r"(addr))
#define LDSM4T(r0, r1, r2, r3, addr)                                          \
    asm volatile("ldmatrix.sync.aligned.m8n8.x4.trans.shared.b16 {%0,%1,%2,%3},[%4];" \
        : "=r"(r0), "=r"(r1), "=r"(r2), "=r"(r3) : "r"(addr))
#define MMAF(d, a, b0, b1)                                                    \
    asm volatile("mma.sync.aligned.m16n8k16.row.col.f32.f16.f16.f32 "         \
        "{%0,%1,%2,%3},{%4,%5,%6,%7},{%8,%9},{%0,%1,%2,%3};"                  \
        : "+f"((d)[0]), "+f"((d)[1]), "+f"((d)[2]), "+f"((d)[3])              \
        : "r"((a)[0]), "r"((a)[1]), "r"((a)[2]), "r"((a)[3]), "r"(b0), "r"(b1))

__device__ __forceinline__ unsigned pack2h(__half a, __half b) {
    return (unsigned)__half_as_ushort(a) | ((unsigned)__half_as_ushort(b) << 16);
}
__device__ __forceinline__ void split_sts(char* bh, char* bl, unsigned off,
                                          float4 v) {
    __half hx = __float2half_rn(v.x), hy = __float2half_rn(v.y);
    __half hz = __float2half_rn(v.z), hw = __float2half_rn(v.w);
    __half lx = __float2half_rn(v.x - __half2float(hx));
    __half ly = __float2half_rn(v.y - __half2float(hy));
    __half lz = __float2half_rn(v.z - __half2float(hz));
    __half lw = __float2half_rn(v.w - __half2float(hw));
    unsigned sw = SWZ(off);
    *(uint2*)(bh + sw) = make_uint2(pack2h(hx, hy), pack2h(hz, hw));
    *(uint2*)(bl + sw) = make_uint2(pack2h(lx, ly), pack2h(lz, lw));
}

// ---------------- Cayley: scale-free GJ inverse, register-blocked -----------
#define CLD 68
__global__ __launch_bounds__(32) void cayley_kernel(
    const float* __restrict__ Lin, const float* __restrict__ Rin) {
    __shared__ float C[64 * CLD];
    const int blk = blockIdx.x;
    const float* A = blk < 64 ? Lin + blk * 4096 : Rin + (blk - 64) * 4096;
    __half* Q = blk < 64 ? g_Lq + blk * 4096 : g_Rq + (blk - 64) * 4096;
    const int lane = threadIdx.x;
    const int r0 = lane, r1 = lane + 32;

    for (int e = lane; e < 4096; e += 32) {
        int i = e >> 6, j = e & 63;
        C[i * CLD + j] = ((i == j) ? 1.0f : 0.0f)
                       + 0.5f * (A[i * 64 + j] - A[j * 64 + i]);
    }
    __syncwarp();

    for (int k = 0; k < 64; k++) {
        float piv = __fdividef(1.0f, C[k * CLD + k]);
        float f0 = C[r0 * CLD + k] * piv;
        float f1 = C[r1 * CLD + k] * piv;
        bool u0 = (r0 != k), u1 = (r1 != k);
        __syncwarp();
        #pragma unroll
        for (int h = 0; h < 2; h++) {
            const float4* p4 = (const float4*)(C + k * CLD) + h * 8;
            float4* m0 = (float4*)(C + r0 * CLD) + h * 8;
            float4* m1 = (float4*)(C + r1 * CLD) + h * 8;
            float4 p[8], a[8], b[8];
            #pragma unroll
            for (int c = 0; c < 8; c++) p[c] = p4[c];
            #pragma unroll
            for (int c = 0; c < 8; c++) a[c] = m0[c];
            #pragma unroll
            for (int c = 0; c < 8; c++) b[c] = m1[c];
            #pragma unroll
            for (int c = 0; c < 8; c++) {
                a[c].x -= f0 * p[c].x; a[c].y -= f0 * p[c].y;
                a[c].z -= f0 * p[c].z; a[c].w -= f0 * p[c].w;
                b[c].x -= f1 * p[c].x; b[c].y -= f1 * p[c].y;
                b[c].z -= f1 * p[c].z; b[c].w -= f1 * p[c].w;
            }
            if (u0) {
                #pragma unroll
                for (int c = 0; c < 8; c++) m0[c] = a[c];
            }
            if (u1) {
                #pragma unroll
                for (int c = 0; c < 8; c++) m1[c] = b[c];
            }
        }
        if (u0) C[r0 * CLD + k] = -f0;
        else  { C[r0 * CLD + k] = 1.0f; C[r0 * CLD + 64] = piv; }
        if (u1) C[r1 * CLD + k] = -f1;
        else  { C[r1 * CLD + k] = 1.0f; C[r1 * CLD + 64] = piv; }
        __syncwarp();
    }

    for (int e = lane; e < 4096; e += 32) {
        int a = e >> 6, b = e & 63;
        float v = 2.0f * C[b * CLD + 64] * C[b * CLD + a] - (a == b ? 1.0f : 0.0f);
        Q[e] = __float2half_rn(v);
    }
}

// ---------------- Stage 1: M=128(b) N=64(l) K=64(p), 2-term ----------------
#define S1_AHI 0
#define S1_ALO 16384
#define S1_BH  32768
#define S1_SMEM 40960

__global__ __launch_bounds__(256, 2) void stage1_kernel(const float* __restrict__ x) {
    extern __shared__ char sm[];
    const unsigned sb = smem_u32(sm);
    const int tid = threadIdx.x, wid = tid >> 5, lane = tid & 31;
    const int rblk = blockIdx.x;
    const long b0 = (long)blockIdx.y * 128;

    #pragma unroll
    for (int q = 0; q < 8; q++) {
        int f = q * 256 + tid;
        int row = f >> 4, p4 = f & 15;
        float4 v = *(const float4*)(x + (b0 + row) * 4096 + rblk * 64 + p4 * 4);
        split_sts(sm + S1_AHI, sm + S1_ALO, (unsigned)(row * 128 + p4 * 8), v);
    }
    #pragma unroll
    for (int q = 0; q < 4; q++) {
        int f = q * 256 + tid;
        int row = f >> 4, c4 = f & 15;
        uint2 u = *(const uint2*)((const __half*)g_Rq + (size_t)rblk * 4096 + f * 4);
        *(uint2*)(sm + S1_BH + SWZ((unsigned)(row * 128 + c4 * 8))) = u;
    }
    __syncthreads();

    const int wm = wid & 3, wn = wid >> 2;
    const int M0 = wm * 32, N0 = wn * 32;
    float acc[2][4][4] = {};

    #pragma unroll
    for (int kk = 0; kk < 4; kk++) {
        const unsigned kb = kk * 32;
        unsigned ah[2][4], al[2][4];
        #pragma unroll
        for (int mt = 0; mt < 2; mt++) {
            unsigned row = M0 + mt * 16 + (lane & 15);
            unsigned ph = SWZ(row * 128 + kb + ((lane >> 4) << 4));
            LDSM4(ah[mt][0], ah[mt][1], ah[mt][2], ah[mt][3], sb + S1_AHI + ph);
            LDSM4(al[mt][0], al[mt][1], al[mt][2], al[mt][3], sb + S1_ALO + ph);
        }
        unsigned bh[2][4];
        #pragma unroll
        for (int nh = 0; nh < 2; nh++) {
            unsigned row = N0 + nh * 16 + (lane & 7) + ((lane >> 4) << 3);
            unsigned ph = SWZ(row * 128 + kb + (((lane >> 3) & 1) << 4));
            LDSM4(bh[nh][0], bh[nh][1], bh[nh][2], bh[nh][3], sb + S1_BH + ph);
        }
        #pragma unroll
        for (int mt = 0; mt < 2; mt++)
            #pragma unroll
            for (int nh = 0; nh < 2; nh++) {
                MMAF(acc[mt][nh * 2 + 0], ah[mt], bh[nh][0], bh[nh][1]);
                MMAF(acc[mt][nh * 2 + 0], al[mt], bh[nh][0], bh[nh][1]);
                MMAF(acc[mt][nh * 2 + 1], ah[mt], bh[nh][2], bh[nh][3]);
                MMAF(acc[mt][nh * 2 + 1], al[mt], bh[nh][2], bh[nh][3]);
            }
    }

    // epilogue: fp16 STG to g_t[l][r][b]
    const int g = lane >> 2, t2 = (lane & 3) << 1;
    #pragma unroll
    for (int mt = 0; mt < 2; mt++) {
        const long bb = b0 + M0 + mt * 16 + g;
        #pragma unroll
        for (int nt = 0; nt < 4; nt++) {
            int l0 = N0 + nt * 8 + t2;
            size_t base = ((size_t)l0 * 64 + rblk) * 16384;
            g_t[base + bb]               = __float2half_rn(acc[mt][nt][0]);
            g_t[base + 1048576 + bb]     = __float2half_rn(acc[mt][nt][1]);
            g_t[base + bb + 8]           = __float2half_rn(acc[mt][nt][2]);
            g_t[base + 1048576 + bb + 8] = __float2half_rn(acc[mt][nt][3]);
        }
    }
}

// ---------------- Stage 2: 4 l's per CTA, M=64(b) N=64(s) K=64(r), 1-term ---
#define S2_ATH 0
#define S2_BH  8192
#define S2_OS  16384
#define S2_SMEM (16384 + 4 * 64 * 66 * 4)     // 83968

__global__ __launch_bounds__(256, 2) void stage2_kernel(float* __restrict__ y) {
    extern __shared__ char sm[];
    const unsigned sb = smem_u32(sm);
    float* os = (float*)(sm + S2_OS);
    const int tid = threadIdx.x, wid = tid >> 5, lane = tid & 31;
    const int lg = blockIdx.x;                    // 0..15
    const long b0 = (long)blockIdx.y * 64;

    const int wm = wid & 1, wn = wid >> 1;        // warp tile m32 x n16
    const int M0 = wm * 32, N0 = wn * 16;
    const int g = lane >> 2, t2 = (lane & 3) << 1;

    uint2 abuf[4], wbuf[4];
    #pragma unroll
    for (int q = 0; q < 4; q++) {                 // prefetch ll=0
        int f = q * 256 + tid;                    // 0..1023
        int r = f >> 4, b4 = f & 15;
        abuf[q] = *(const uint2*)(g_t + ((size_t)(lg * 4) * 64 + r) * 16384
                                      + b0 + b4 * 4);
        wbuf[q] = *(const uint2*)(g_Lq + (size_t)(lg * 4) * 4096 + f * 4);
    }

    for (int ll = 0; ll < 4; ll++) {
        #pragma unroll
        for (int q = 0; q < 4; q++) {
            int f = q * 256 + tid;
            int r = f >> 4, b4 = f & 15;
            unsigned sw = SWZ((unsigned)(r * 128 + b4 * 8));
            *(uint2*)(sm + S2_ATH + sw) = abuf[q];   // At[r][b] fp16
            *(uint2*)(sm + S2_BH  + sw) = wbuf[q];   // W[s][r] fp16
        }
        __syncthreads();
        if (ll < 3) {
            const int l = lg * 4 + ll + 1;
            #pragma unroll
            for (int q = 0; q < 4; q++) {
                int f = q * 256 + tid;
                int r = f >> 4, b4 = f & 15;
                abuf[q] = *(const uint2*)(g_t + ((size_t)l * 64 + r) * 16384
                                              + b0 + b4 * 4);
                wbuf[q] = *(const uint2*)(g_Lq + (size_t)l * 4096 + f * 4);
            }
        }

        float acc[2][2][4] = {};
        #pragma unroll
        for (int kk = 0; kk < 4; kk++) {
            unsigned ah[2][4];
            #pragma unroll
            for (int mt = 0; mt < 2; mt++) {       // A via ldmatrix.trans
                unsigned row = kk * 16 + (lane & 7) + ((lane >> 4) << 3);
                unsigned cb = (M0 + mt * 16 + (((lane >> 3) & 1) << 3)) * 2;
                unsigned ph = SWZ(row * 128 + cb);
                LDSM4T(ah[mt][0], ah[mt][1], ah[mt][2], ah[mt][3], sb + S2_ATH + ph);
            }
            unsigned bh[4];
            {
                unsigned row = N0 + (lane & 7) + ((lane >> 4) << 3);
                unsigned ph = SWZ(row * 128 + kk * 32 + (((lane >> 3) & 1) << 4));
                LDSM4(bh[0], bh[1], bh[2], bh[3], sb + S2_BH + ph);
            }
            #pragma unroll
            for (int mt = 0; mt < 2; mt++) {
                MMAF(acc[mt][0], ah[mt], bh[0], bh[1]);
                MMAF(acc[mt][1], ah[mt], bh[2], bh[3]);
            }
        }

        #pragma unroll
        for (int mt = 0; mt < 2; mt++)
            #pragma unroll
            for (int nt = 0; nt < 2; nt++) {
                float* p = os + ll * 4224 + (M0 + mt * 16 + g) * 66
                              + N0 + nt * 8 + t2;
                *(float2*)p = make_float2(acc[mt][nt][0], acc[mt][nt][1]);
                *(float2*)(p + 8 * 66) = make_float2(acc[mt][nt][2], acc[mt][nt][3]);
            }
        __syncthreads();
    }

    for (int e = tid; e < 4096; e += 256) {
        int b = e >> 6, s = e & 63;
        int idx = b * 66 + s;
        float4 v = make_float4(os[idx], os[4224 + idx],
                               os[8448 + idx], os[12672 + idx]);
        *(float4*)(y + (b0 + b) * 4096 + s * 64 + lg * 4) = v;
    }
}

// ---------------------------------------------------------------------------
extern "C" void kernel_launch(void* const* d_in, const int* in_sizes, int n_in,
                              void* d_out, int out_size) {
    const float* x = (const float*)d_in[0];
    const float* L = (const float*)d_in[1];
    const float* R = (const float*)d_in[2];
    float* y = (float*)d_out;

    cudaFuncSetAttribute(stage1_kernel,
                         cudaFuncAttributeMaxDynamicSharedMemorySize, S1_SMEM);
    cudaFuncSetAttribute(stage2_kernel,
                         cudaFuncAttributeMaxDynamicSharedMemorySize, S2_SMEM);

    cayley_kernel<<<128, 32>>>(L, R);
    stage1_kernel<<<dim3(64, 128), 256, S1_SMEM>>>(x);
    stage2_kernel<<<dim3(16, 256), 256, S2_SMEM>>>(y);
}

// round 11
// speedup vs baseline: 4.3845x; 1.0424x over previous
#include <cuda_runtime.h>
#include <cuda_fp16.h>

// ---------------------------------------------------------------------------
// GSOrthogonal round 11: pure fp16 operands (1-term) in both stages.
//  stage1: g_t[l][r][b] = sum_p Rq[r][l][p] x[b][r*64+p]   (fp16 in, f32 acc)
//  stage2: y[b][s*64+l] = sum_r Lq[l][s][r] t[l][r][b]
//  rel_err budget: W quant ~2e-4/stage + x/t quant ~1.4e-4 each -> ~4e-4.
// ---------------------------------------------------------------------------

__device__ __half g_Lq[64 * 64 * 64];            // fp16 weights
__device__ __half g_Rq[64 * 64 * 64];
__device__ __half g_t[(size_t)4096 * 16384];     // [l][r][b] fp16

__device__ __forceinline__ unsigned smem_u32(const void* p) {
    unsigned a;
    asm("{ .reg .u64 t; cvta.to.shared.u64 t, %1; cvt.u32.u64 %0, t; }"
        : "=r"(a) : "l"(p));
    return a;
}

#define SWZ(o) ((o) ^ (((o) >> 3) & 0x70u))

#define LDSM4(r0, r1, r2, r3, addr)                                           \
    asm volatile("ldmatrix.sync.aligned.m8n8.x4.shared.b16 {%0,%1,%2,%3},[%4];" \
        : "=r"(r0), "=r"(r1), "=r"(r2), "=r"(r3) : "r"(addr))
#define LDSM4T(r0, r1, r2, r3, addr)                                          \
    asm volatile("ldmatrix.sync.aligned.m8n8.x4.trans.shared.b16 {%0,%1,%2,%3},[%4];" \
        : "=r"(r0), "=r"(r1), "=r"(r2), "=r"(r3) : "r"(addr))
#define MMAF(d, a, b0, b1)                                                    \
    asm volatile("mma.sync.aligned.m16n8k16.row.col.f32.f16.f16.f32 "         \
        "{%0,%1,%2,%3},{%4,%5,%6,%7},{%8,%9},{%0,%1,%2,%3};"                  \
        : "+f"((d)[0]), "+f"((d)[1]), "+f"((d)[2]), "+f"((d)[3])              \
        : "r"((a)[0]), "r"((a)[1]), "r"((a)[2]), "r"((a)[3]), "r"(b0), "r"(b1))

__device__ __forceinline__ unsigned pack2h(__half a, __half b) {
    return (unsigned)__half_as_ushort(a) | ((unsigned)__half_as_ushort(b) << 16);
}

// ---------------- Cayley: scale-free GJ inverse, register-blocked -----------
#define CLD 68
__global__ __launch_bounds__(32) void cayley_kernel(
    const float* __restrict__ Lin, const float* __restrict__ Rin) {
    __shared__ float C[64 * CLD];
    const int blk = blockIdx.x;
    const float* A = blk < 64 ? Lin + blk * 4096 : Rin + (blk - 64) * 4096;
    __half* Q = blk < 64 ? g_Lq + blk * 4096 : g_Rq + (blk - 64) * 4096;
    const int lane = threadIdx.x;
    const int r0 = lane, r1 = lane + 32;

    for (int e = lane; e < 4096; e += 32) {
        int i = e >> 6, j = e & 63;
        C[i * CLD + j] = ((i == j) ? 1.0f : 0.0f)
                       + 0.5f * (A[i * 64 + j] - A[j * 64 + i]);
    }
    __syncwarp();

    for (int k = 0; k < 64; k++) {
        float piv = __fdividef(1.0f, C[k * CLD + k]);
        float f0 = C[r0 * CLD + k] * piv;
        float f1 = C[r1 * CLD + k] * piv;
        bool u0 = (r0 != k), u1 = (r1 != k);
        __syncwarp();
        #pragma unroll
        for (int h = 0; h < 2; h++) {
            const float4* p4 = (const float4*)(C + k * CLD) + h * 8;
            float4* m0 = (float4*)(C + r0 * CLD) + h * 8;
            float4* m1 = (float4*)(C + r1 * CLD) + h * 8;
            float4 p[8], a[8], b[8];
            #pragma unroll
            for (int c = 0; c < 8; c++) p[c] = p4[c];
            #pragma unroll
            for (int c = 0; c < 8; c++) a[c] = m0[c];
            #pragma unroll
            for (int c = 0; c < 8; c++) b[c] = m1[c];
            #pragma unroll
            for (int c = 0; c < 8; c++) {
                a[c].x -= f0 * p[c].x; a[c].y -= f0 * p[c].y;
                a[c].z -= f0 * p[c].z; a[c].w -= f0 * p[c].w;
                b[c].x -= f1 * p[c].x; b[c].y -= f1 * p[c].y;
                b[c].z -= f1 * p[c].z; b[c].w -= f1 * p[c].w;
            }
            if (u0) {
                #pragma unroll
                for (int c = 0; c < 8; c++) m0[c] = a[c];
            }
            if (u1) {
                #pragma unroll
                for (int c = 0; c < 8; c++) m1[c] = b[c];
            }
        }
        if (u0) C[r0 * CLD + k] = -f0;
        else  { C[r0 * CLD + k] = 1.0f; C[r0 * CLD + 64] = piv; }
        if (u1) C[r1 * CLD + k] = -f1;
        else  { C[r1 * CLD + k] = 1.0f; C[r1 * CLD + 64] = piv; }
        __syncwarp();
    }

    for (int e = lane; e < 4096; e += 32) {
        int a = e >> 6, b = e & 63;
        float v = 2.0f * C[b * CLD + 64] * C[b * CLD + a] - (a == b ? 1.0f : 0.0f);
        Q[e] = __float2half_rn(v);
    }
}

// ---------------- Stage 1: M=128(b) N=64(l) K=64(p), 1-term -----------------
#define S1_AH  0
#define S1_BH  16384
#define S1_SMEM 24576

__global__ __launch_bounds__(256, 2) void stage1_kernel(const float* __restrict__ x) {
    extern __shared__ char sm[];
    const unsigned sb = smem_u32(sm);
    const int tid = threadIdx.x, wid = tid >> 5, lane = tid & 31;
    const int rblk = blockIdx.x;
    const long b0 = (long)blockIdx.y * 128;

    // A = x tile 128x64, converted to fp16
    #pragma unroll
    for (int q = 0; q < 8; q++) {
        int f = q * 256 + tid;
        int row = f >> 4, p4 = f & 15;
        float4 v = *(const float4*)(x + (b0 + row) * 4096 + rblk * 64 + p4 * 4);
        uint2 h = make_uint2(pack2h(__float2half_rn(v.x), __float2half_rn(v.y)),
                             pack2h(__float2half_rn(v.z), __float2half_rn(v.w)));
        *(uint2*)(sm + S1_AH + SWZ((unsigned)(row * 128 + p4 * 8))) = h;
    }
    // B = Rq[rblk] 64x64 fp16
    #pragma unroll
    for (int q = 0; q < 4; q++) {
        int f = q * 256 + tid;
        int row = f >> 4, c4 = f & 15;
        uint2 u = *(const uint2*)(g_Rq + (size_t)rblk * 4096 + f * 4);
        *(uint2*)(sm + S1_BH + SWZ((unsigned)(row * 128 + c4 * 8))) = u;
    }
    __syncthreads();

    const int wm = wid & 3, wn = wid >> 2;
    const int M0 = wm * 32, N0 = wn * 32;
    float acc[2][4][4] = {};

    #pragma unroll
    for (int kk = 0; kk < 4; kk++) {
        const unsigned kb = kk * 32;
        unsigned ah[2][4];
        #pragma unroll
        for (int mt = 0; mt < 2; mt++) {
            unsigned row = M0 + mt * 16 + (lane & 15);
            unsigned ph = SWZ(row * 128 + kb + ((lane >> 4) << 4));
            LDSM4(ah[mt][0], ah[mt][1], ah[mt][2], ah[mt][3], sb + S1_AH + ph);
        }
        unsigned bh[2][4];
        #pragma unroll
        for (int nh = 0; nh < 2; nh++) {
            unsigned row = N0 + nh * 16 + (lane & 7) + ((lane >> 4) << 3);
            unsigned ph = SWZ(row * 128 + kb + (((lane >> 3) & 1) << 4));
            LDSM4(bh[nh][0], bh[nh][1], bh[nh][2], bh[nh][3], sb + S1_BH + ph);
        }
        #pragma unroll
        for (int mt = 0; mt < 2; mt++)
            #pragma unroll
            for (int nh = 0; nh < 2; nh++) {
                MMAF(acc[mt][nh * 2 + 0], ah[mt], bh[nh][0], bh[nh][1]);
                MMAF(acc[mt][nh * 2 + 1], ah[mt], bh[nh][2], bh[nh][3]);
            }
    }

    // epilogue: fp16 STG to g_t[l][r][b]
    const int g = lane >> 2, t2 = (lane & 3) << 1;
    #pragma unroll
    for (int mt = 0; mt < 2; mt++) {
        const long bb = b0 + M0 + mt * 16 + g;
        #pragma unroll
        for (int nt = 0; nt < 4; nt++) {
            int l0 = N0 + nt * 8 + t2;
            size_t base = ((size_t)l0 * 64 + rblk) * 16384;
            g_t[base + bb]               = __float2half_rn(acc[mt][nt][0]);
            g_t[base + 1048576 + bb]     = __float2half_rn(acc[mt][nt][1]);
            g_t[base + bb + 8]           = __float2half_rn(acc[mt][nt][2]);
            g_t[base + 1048576 + bb + 8] = __float2half_rn(acc[mt][nt][3]);
        }
    }
}

// ---------------- Stage 2: 4 l's per CTA, M=64(b) N=64(s) K=64(r), 1-term ---
#define S2_ATH 0
#define S2_BH  8192
#define S2_OS  16384
#define S2_SMEM (16384 + 4 * 64 * 66 * 4)     // 83968

__global__ __launch_bounds__(256, 2) void stage2_kernel(float* __restrict__ y) {
    extern __shared__ char sm[];
    const unsigned sb = smem_u32(sm);
    float* os = (float*)(sm + S2_OS);
    const int tid = threadIdx.x, wid = tid >> 5, lane = tid & 31;
    const int lg = blockIdx.x;                    // 0..15
    const long b0 = (long)blockIdx.y * 64;

    const int wm = wid & 1, wn = wid >> 1;        // warp tile m32 x n16
    const int M0 = wm * 32, N0 = wn * 16;
    const int g = lane >> 2, t2 = (lane & 3) << 1;

    uint2 abuf[4], wbuf[4];
    #pragma unroll
    for (int q = 0; q < 4; q++) {                 // prefetch ll=0
        int f = q * 256 + tid;
        int r = f >> 4, b4 = f & 15;
        abuf[q] = *(const uint2*)(g_t + ((size_t)(lg * 4) * 64 + r) * 16384
                                      + b0 + b4 * 4);
        wbuf[q] = *(const uint2*)(g_Lq + (size_t)(lg * 4) * 4096 + f * 4);
    }

    for (int ll = 0; ll < 4; ll++) {
        #pragma unroll
        for (int q = 0; q < 4; q++) {
            int f = q * 256 + tid;
            int r = f >> 4, b4 = f & 15;
            unsigned sw = SWZ((unsigned)(r * 128 + b4 * 8));
            *(uint2*)(sm + S2_ATH + sw) = abuf[q];   // At[r][b] fp16
            *(uint2*)(sm + S2_BH  + sw) = wbuf[q];   // W[s][r] fp16
        }
        __syncthreads();
        if (ll < 3) {
            const int l = lg * 4 + ll + 1;
            #pragma unroll
            for (int q = 0; q < 4; q++) {
                int f = q * 256 + tid;
                int r = f >> 4, b4 = f & 15;
                abuf[q] = *(const uint2*)(g_t + ((size_t)l * 64 + r) * 16384
                                              + b0 + b4 * 4);
                wbuf[q] = *(const uint2*)(g_Lq + (size_t)l * 4096 + f * 4);
            }
        }

        float acc[2][2][4] = {};
        #pragma unroll
        for (int kk = 0; kk < 4; kk++) {
            unsigned ah[2][4];
            #pragma unroll
            for (int mt = 0; mt < 2; mt++) {       // A via ldmatrix.trans
                unsigned row = kk * 16 + (lane & 7) + ((lane >> 4) << 3);
                unsigned cb = (M0 + mt * 16 + (((lane >> 3) & 1) << 3)) * 2;
                unsigned ph = SWZ(row * 128 + cb);
                LDSM4T(ah[mt][0], ah[mt][1], ah[mt][2], ah[mt][3], sb + S2_ATH + ph);
            }
            unsigned bh[4];
            {
                unsigned row = N0 + (lane & 7) + ((lane >> 4) << 3);
                unsigned ph = SWZ(row * 128 + kk * 32 + (((lane >> 3) & 1) << 4));
                LDSM4(bh[0], bh[1], bh[2], bh[3], sb + S2_BH + ph);
            }
            #pragma unroll
            for (int mt = 0; mt < 2; mt++) {
                MMAF(acc[mt][0], ah[mt], bh[0], bh[1]);
                MMAF(acc[mt][1], ah[mt], bh[2], bh[3]);
            }
        }

        #pragma unroll
        for (int mt = 0; mt < 2; mt++)
            #pragma unroll
            for (int nt = 0; nt < 2; nt++) {
                float* p = os + ll * 4224 + (M0 + mt * 16 + g) * 66
                              + N0 + nt * 8 + t2;
                *(float2*)p = make_float2(acc[mt][nt][0], acc[mt][nt][1]);
                *(float2*)(p + 8 * 66) = make_float2(acc[mt][nt][2], acc[mt][nt][3]);
            }
        __syncthreads();
    }

    for (int e = tid; e < 4096; e += 256) {
        int b = e >> 6, s = e & 63;
        int idx = b * 66 + s;
        float4 v = make_float4(os[idx], os[4224 + idx],
                               os[8448 + idx], os[12672 + idx]);
        *(float4*)(y + (b0 + b) * 4096 + s * 64 + lg * 4) = v;
    }
}

// ---------------------------------------------------------------------------
extern "C" void kernel_launch(void* const* d_in, const int* in_sizes, int n_in,
                              void* d_out, int out_size) {
    const float* x = (const float*)d_in[0];
    const float* L = (const float*)d_in[1];
    const float* R = (const float*)d_in[2];
    float* y = (float*)d_out;

    cudaFuncSetAttribute(stage1_kernel,
                         cudaFuncAttributeMaxDynamicSharedMemorySize, S1_SMEM);
    cudaFuncSetAttribute(stage2_kernel,
                         cudaFuncAttributeMaxDynamicSharedMemorySize, S2_SMEM);

    cayley_kernel<<<128, 32>>>(L, R);
    stage1_kernel<<<dim3(64, 128), 256, S1_SMEM>>>(x);
    stage2_kernel<<<dim3(16, 256), 256, S2_SMEM>>>(y);
}

// round 12
// speedup vs baseline: 4.5029x; 1.0270x over previous
#include <cuda_runtime.h>
#include <cuda_fp16.h>

// ---------------------------------------------------------------------------
// GSOrthogonal round 12: latency-pipelined stages (multi-tile CTAs + register
// prefetch + weight amortization). Math identical to round 11 (pure fp16
// operands, f32 accumulate).
//  stage1: g_t[l][r][b] = sum_p Rq[r][l][p] x[b][r*64+p]
//  stage2: y[b][s*64+l] = sum_r Lq[l][s][r] t[l][r][b]
// ---------------------------------------------------------------------------

__device__ __half g_Lq[64 * 64 * 64];
__device__ __half g_Rq[64 * 64 * 64];
__device__ __half g_t[(size_t)4096 * 16384];     // [l][r][b] fp16

__device__ __forceinline__ unsigned smem_u32(const void* p) {
    unsigned a;
    asm("{ .reg .u64 t; cvta.to.shared.u64 t, %1; cvt.u32.u64 %0, t; }"
        : "=r"(a) : "l"(p));
    return a;
}

#define SWZ(o) ((o) ^ (((o) >> 3) & 0x70u))

#define LDSM4(r0, r1, r2, r3, addr)                                           \
    asm volatile("ldmatrix.sync.aligned.m8n8.x4.shared.b16 {%0,%1,%2,%3},[%4];" \
        : "=r"(r0), "=r"(r1), "=r"(r2), "=r"(r3) : "r"(addr))
#define LDSM4T(r0, r1, r2, r3, addr)                                          \
    asm volatile("ldmatrix.sync.aligned.m8n8.x4.trans.shared.b16 {%0,%1,%2,%3},[%4];" \
        : "=r"(r0), "=r"(r1), "=r"(r2), "=r"(r3) : "r"(addr))
#define MMAF(d, a, b0, b1)                                                    \
    asm volatile("mma.sync.aligned.m16n8k16.row.col.f32.f16.f16.f32 "         \
        "{%0,%1,%2,%3},{%4,%5,%6,%7},{%8,%9},{%0,%1,%2,%3};"                  \
        : "+f"((d)[0]), "+f"((d)[1]), "+f"((d)[2]), "+f"((d)[3])              \
        : "r"((a)[0]), "r"((a)[1]), "r"((a)[2]), "r"((a)[3]), "r"(b0), "r"(b1))

__device__ __forceinline__ unsigned pack2h(__half a, __half b) {
    return (unsigned)__half_as_ushort(a) | ((unsigned)__half_as_ushort(b) << 16);
}

// ---------------- Cayley: scale-free GJ inverse, register-blocked -----------
#define CLD 68
__global__ __launch_bounds__(32) void cayley_kernel(
    const float* __restrict__ Lin, const float* __restrict__ Rin) {
    __shared__ float C[64 * CLD];
    const int blk = blockIdx.x;
    const float* A = blk < 64 ? Lin + blk * 4096 : Rin + (blk - 64) * 4096;
    __half* Q = blk < 64 ? g_Lq + blk * 4096 : g_Rq + (blk - 64) * 4096;
    const int lane = threadIdx.x;
    const int r0 = lane, r1 = lane + 32;

    for (int e = lane; e < 4096; e += 32) {
        int i = e >> 6, j = e & 63;
        C[i * CLD + j] = ((i == j) ? 1.0f : 0.0f)
                       + 0.5f * (A[i * 64 + j] - A[j * 64 + i]);
    }
    __syncwarp();

    for (int k = 0; k < 64; k++) {
        float piv = __fdividef(1.0f, C[k * CLD + k]);
        float f0 = C[r0 * CLD + k] * piv;
        float f1 = C[r1 * CLD + k] * piv;
        bool u0 = (r0 != k), u1 = (r1 != k);
        __syncwarp();
        #pragma unroll
        for (int h = 0; h < 2; h++) {
            const float4* p4 = (const float4*)(C + k * CLD) + h * 8;
            float4* m0 = (float4*)(C + r0 * CLD) + h * 8;
            float4* m1 = (float4*)(C + r1 * CLD) + h * 8;
            float4 p[8], a[8], b[8];
            #pragma unroll
            for (int c = 0; c < 8; c++) p[c] = p4[c];
            #pragma unroll
            for (int c = 0; c < 8; c++) a[c] = m0[c];
            #pragma unroll
            for (int c = 0; c < 8; c++) b[c] = m1[c];
            #pragma unroll
            for (int c = 0; c < 8; c++) {
                a[c].x -= f0 * p[c].x; a[c].y -= f0 * p[c].y;
                a[c].z -= f0 * p[c].z; a[c].w -= f0 * p[c].w;
                b[c].x -= f1 * p[c].x; b[c].y -= f1 * p[c].y;
                b[c].z -= f1 * p[c].z; b[c].w -= f1 * p[c].w;
            }
            if (u0) {
                #pragma unroll
                for (int c = 0; c < 8; c++) m0[c] = a[c];
            }
            if (u1) {
                #pragma unroll
                for (int c = 0; c < 8; c++) m1[c] = b[c];
            }
        }
        if (u0) C[r0 * CLD + k] = -f0;
        else  { C[r0 * CLD + k] = 1.0f; C[r0 * CLD + 64] = piv; }
        if (u1) C[r1 * CLD + k] = -f1;
        else  { C[r1 * CLD + k] = 1.0f; C[r1 * CLD + 64] = piv; }
        __syncwarp();
    }

    for (int e = lane; e < 4096; e += 32) {
        int a = e >> 6, b = e & 63;
        float v = 2.0f * C[b * CLD + 64] * C[b * CLD + a] - (a == b ? 1.0f : 0.0f);
        Q[e] = __float2half_rn(v);
    }
}

// ---------------- Stage 1: 4 b-tiles/CTA, M=128(b) N=64(l) K=64(p) ----------
#define S1_AH  0
#define S1_BH  16384
#define S1_SMEM 24576
#define S1_TILES 4

__global__ __launch_bounds__(256, 2) void stage1_kernel(const float* __restrict__ x) {
    extern __shared__ char sm[];
    const unsigned sb = smem_u32(sm);
    const int tid = threadIdx.x, wid = tid >> 5, lane = tid & 31;
    const int rblk = blockIdx.x;
    const long bbase = (long)blockIdx.y * (128 * S1_TILES);

    // B = Rq[rblk], loaded once
    #pragma unroll
    for (int q = 0; q < 4; q++) {
        int f = q * 256 + tid;
        int row = f >> 4, c4 = f & 15;
        uint2 u = *(const uint2*)(g_Rq + (size_t)rblk * 4096 + f * 4);
        *(uint2*)(sm + S1_BH + SWZ((unsigned)(row * 128 + c4 * 8))) = u;
    }

    // prefetch x tile 0 into registers
    float4 xbuf[8];
    #pragma unroll
    for (int q = 0; q < 8; q++) {
        int f = q * 256 + tid;
        int row = f >> 4, p4 = f & 15;
        xbuf[q] = *(const float4*)(x + (bbase + row) * 4096 + rblk * 64 + p4 * 4);
    }

    const int wm = wid & 3, wn = wid >> 2;
    const int M0 = wm * 32, N0 = wn * 32;
    const int g = lane >> 2, t2 = (lane & 3) << 1;

    for (int tb = 0; tb < S1_TILES; tb++) {
        const long b0 = bbase + tb * 128;
        // stage registers -> smem (fp16)
        #pragma unroll
        for (int q = 0; q < 8; q++) {
            int f = q * 256 + tid;
            int row = f >> 4, p4 = f & 15;
            float4 v = xbuf[q];
            uint2 h = make_uint2(pack2h(__float2half_rn(v.x), __float2half_rn(v.y)),
                                 pack2h(__float2half_rn(v.z), __float2half_rn(v.w)));
            *(uint2*)(sm + S1_AH + SWZ((unsigned)(row * 128 + p4 * 8))) = h;
        }
        __syncthreads();
        // prefetch next tile (overlaps LDSM/MMA/epilogue below)
        if (tb + 1 < S1_TILES) {
            #pragma unroll
            for (int q = 0; q < 8; q++) {
                int f = q * 256 + tid;
                int row = f >> 4, p4 = f & 15;
                xbuf[q] = *(const float4*)(x + (b0 + 128 + row) * 4096
                                             + rblk * 64 + p4 * 4);
            }
        }

        float acc[2][4][4] = {};
        #pragma unroll
        for (int kk = 0; kk < 4; kk++) {
            const unsigned kb = kk * 32;
            unsigned ah[2][4];
            #pragma unroll
            for (int mt = 0; mt < 2; mt++) {
                unsigned row = M0 + mt * 16 + (lane & 15);
                unsigned ph = SWZ(row * 128 + kb + ((lane >> 4) << 4));
                LDSM4(ah[mt][0], ah[mt][1], ah[mt][2], ah[mt][3], sb + S1_AH + ph);
            }
            unsigned bh[2][4];
            #pragma unroll
            for (int nh = 0; nh < 2; nh++) {
                unsigned row = N0 + nh * 16 + (lane & 7) + ((lane >> 4) << 3);
                unsigned ph = SWZ(row * 128 + kb + (((lane >> 3) & 1) << 4));
                LDSM4(bh[nh][0], bh[nh][1], bh[nh][2], bh[nh][3], sb + S1_BH + ph);
            }
            #pragma unroll
            for (int mt = 0; mt < 2; mt++)
                #pragma unroll
                for (int nh = 0; nh < 2; nh++) {
                    MMAF(acc[mt][nh * 2 + 0], ah[mt], bh[nh][0], bh[nh][1]);
                    MMAF(acc[mt][nh * 2 + 1], ah[mt], bh[nh][2], bh[nh][3]);
                }
        }

        // epilogue: fp16 STG to g_t[l][r][b]
        #pragma unroll
        for (int mt = 0; mt < 2; mt++) {
            const long bb = b0 + M0 + mt * 16 + g;
            #pragma unroll
            for (int nt = 0; nt < 4; nt++) {
                int l0 = N0 + nt * 8 + t2;
                size_t base = ((size_t)l0 * 64 + rblk) * 16384;
                g_t[base + bb]               = __float2half_rn(acc[mt][nt][0]);
                g_t[base + 1048576 + bb]     = __float2half_rn(acc[mt][nt][1]);
                g_t[base + bb + 8]           = __float2half_rn(acc[mt][nt][2]);
                g_t[base + 1048576 + bb + 8] = __float2half_rn(acc[mt][nt][3]);
            }
        }
        __syncthreads();   // A smem reads + epilogue done before next STS
    }
}

// ---------------- Stage 2: 2 b-tiles x 4 l's per CTA -------------------------
// smem: W 4 planes (32KB) @0, At (8KB) @32768, os 4x64x66 f32 @40960
#define S2_W   0
#define S2_ATH 32768
#define S2_OS  40960
#define S2_SMEM (40960 + 4 * 64 * 66 * 4)     // 108544
#define S2_TILES 2

__global__ __launch_bounds__(256, 2) void stage2_kernel(float* __restrict__ y) {
    extern __shared__ char sm[];
    const unsigned sb = smem_u32(sm);
    float* os = (float*)(sm + S2_OS);
    const int tid = threadIdx.x, wid = tid >> 5, lane = tid & 31;
    const int lg = blockIdx.x;                    // 0..15
    const long bbase = (long)blockIdx.y * (64 * S2_TILES);

    const int wm = wid & 1, wn = wid >> 1;        // warp tile m32 x n16
    const int M0 = wm * 32, N0 = wn * 16;
    const int g = lane >> 2, t2 = (lane & 3) << 1;

    // preload all 4 weight planes (once per CTA)
    #pragma unroll
    for (int q = 0; q < 16; q++) {
        int f = q * 256 + tid;                    // 0..4095
        int pl = f >> 10, e = f & 1023;
        int r = e >> 4, b4 = e & 15;
        uint2 u = *(const uint2*)(g_Lq + (size_t)(lg * 4 + pl) * 4096 + e * 4);
        *(uint2*)(sm + S2_W + pl * 8192 + SWZ((unsigned)(r * 128 + b4 * 8))) = u;
    }

    // prefetch A for (tbi=0, ll=0)
    uint2 abuf[4];
    #pragma unroll
    for (int q = 0; q < 4; q++) {
        int f = q * 256 + tid;
        int r = f >> 4, b4 = f & 15;
        abuf[q] = *(const uint2*)(g_t + ((size_t)(lg * 4) * 64 + r) * 16384
                                      + bbase + b4 * 4);
    }
    __syncthreads();   // W planes visible

    for (int tbi = 0; tbi < S2_TILES; tbi++) {
        const long b0 = bbase + tbi * 64;
        for (int ll = 0; ll < 4; ll++) {
            #pragma unroll
            for (int q = 0; q < 4; q++) {
                int f = q * 256 + tid;
                int r = f >> 4, b4 = f & 15;
                *(uint2*)(sm + S2_ATH + SWZ((unsigned)(r * 128 + b4 * 8))) = abuf[q];
            }
            __syncthreads();
            // prefetch next (tbi,ll) in the 8-step chain
            int nxt = tbi * 4 + ll + 1;
            if (nxt < S2_TILES * 4) {
                int tn = nxt >> 2, ln = nxt & 3;
                const long bn = bbase + tn * 64;
                #pragma unroll
                for (int q = 0; q < 4; q++) {
                    int f = q * 256 + tid;
                    int r = f >> 4, b4 = f & 15;
                    abuf[q] = *(const uint2*)(g_t
                        + ((size_t)(lg * 4 + ln) * 64 + r) * 16384 + bn + b4 * 4);
                }
            }

            float acc[2][2][4] = {};
            #pragma unroll
            for (int kk = 0; kk < 4; kk++) {
                unsigned ah[2][4];
                #pragma unroll
                for (int mt = 0; mt < 2; mt++) {   // A via ldmatrix.trans
                    unsigned row = kk * 16 + (lane & 7) + ((lane >> 4) << 3);
                    unsigned cb = (M0 + mt * 16 + (((lane >> 3) & 1) << 3)) * 2;
                    unsigned ph = SWZ(row * 128 + cb);
                    LDSM4T(ah[mt][0], ah[mt][1], ah[mt][2], ah[mt][3],
                           sb + S2_ATH + ph);
                }
                unsigned bh[4];
                {
                    unsigned row = N0 + (lane & 7) + ((lane >> 4) << 3);
                    unsigned ph = SWZ(row * 128 + kk * 32 + (((lane >> 3) & 1) << 4));
                    LDSM4(bh[0], bh[1], bh[2], bh[3], sb + S2_W + ll * 8192 + ph);
                }
                #pragma unroll
                for (int mt = 0; mt < 2; mt++) {
                    MMAF(acc[mt][0], ah[mt], bh[0], bh[1]);
                    MMAF(acc[mt][1], ah[mt], bh[2], bh[3]);
                }
            }

            #pragma unroll
            for (int mt = 0; mt < 2; mt++)
                #pragma unroll
                for (int nt = 0; nt < 2; nt++) {
                    float* p = os + ll * 4224 + (M0 + mt * 16 + g) * 66
                                  + N0 + nt * 8 + t2;
                    *(float2*)p = make_float2(acc[mt][nt][0], acc[mt][nt][1]);
                    *(float2*)(p + 8 * 66) = make_float2(acc[mt][nt][2],
                                                         acc[mt][nt][3]);
                }
            __syncthreads();
        }

        // gather 4 l's per (b,s) -> one float4
        for (int e = tid; e < 4096; e += 256) {
            int b = e >> 6, s = e & 63;
            int idx = b * 66 + s;
            float4 v = make_float4(os[idx], os[4224 + idx],
                                   os[8448 + idx], os[12672 + idx]);
            *(float4*)(y + (b0 + b) * 4096 + s * 64 + lg * 4) = v;
        }
        if (tbi + 1 < S2_TILES) __syncthreads();  // os reads done before reuse
    }
}

// ---------------------------------------------------------------------------
extern "C" void kernel_launch(void* const* d_in, const int* in_sizes, int n_in,
                              void* d_out, int out_size) {
    const float* x = (const float*)d_in[0];
    const float* L = (const float*)d_in[1];
    const float* R = (const float*)d_in[2];
    float* y = (float*)d_out;

    cudaFuncSetAttribute(stage1_kernel,
                         cudaFuncAttributeMaxDynamicSharedMemorySize, S1_SMEM);
    cudaFuncSetAttribute(stage2_kernel,
                         cudaFuncAttributeMaxDynamicSharedMemorySize, S2_SMEM);

    cayley_kernel<<<128, 32>>>(L, R);
    stage1_kernel<<<dim3(64, 32), 256, S1_SMEM>>>(x);
    stage2_kernel<<<dim3(16, 128), 256, S2_SMEM>>>(y);
}

// round 13
// speedup vs baseline: 4.5333x; 1.0067x over previous
#include <cuda_runtime.h>
#include <cuda_fp16.h>

// ---------------------------------------------------------------------------
// GSOrthogonal round 13: LSU/barrier diet. Same math as round 11/12 (pure
// fp16 operands, f32 acc). Stage1: B-fragments hoisted per CTA + double-
// buffered A tile (1 sync/tile). Stage2: all 4 W-plane fragments hoisted per
// CTA + double-buffered At (1 sync/iter), W staging overlaid on os smem.
//  stage1: g_t[l][r][b] = sum_p Rq[r][l][p] x[b][r*64+p]
//  stage2: y[b][s*64+l] = sum_r Lq[l][s][r] t[l][r][b]
// ---------------------------------------------------------------------------

__device__ __half g_Lq[64 * 64 * 64];
__device__ __half g_Rq[64 * 64 * 64];
__device__ __half g_t[(size_t)4096 * 16384];     // [l][r][b] fp16

__device__ __forceinline__ unsigned smem_u32(const void* p) {
    unsigned a;
    asm("{ .reg .u64 t; cvta.to.shared.u64 t, %1; cvt.u32.u64 %0, t; }"
        : "=r"(a) : "l"(p));
    return a;
}

#define SWZ(o) ((o) ^ (((o) >> 3) & 0x70u))

#define LDSM4(r0, r1, r2, r3, addr)                                           \
    asm volatile("ldmatrix.sync.aligned.m8n8.x4.shared.b16 {%0,%1,%2,%3},[%4];" \
        : "=r"(r0), "=r"(r1), "=r"(r2), "=r"(r3) : "r"(addr))
#define LDSM4T(r0, r1, r2, r3, addr)                                          \
    asm volatile("ldmatrix.sync.aligned.m8n8.x4.trans.shared.b16 {%0,%1,%2,%3},[%4];" \
        : "=r"(r0), "=r"(r1), "=r"(r2), "=r"(r3) : "r"(addr))
#define MMAF(d, a, b0, b1)                                                    \
    asm volatile("mma.sync.aligned.m16n8k16.row.col.f32.f16.f16.f32 "         \
        "{%0,%1,%2,%3},{%4,%5,%6,%7},{%8,%9},{%0,%1,%2,%3};"                  \
        : "+f"((d)[0]), "+f"((d)[1]), "+f"((d)[2]), "+f"((d)[3])              \
        : "r"((a)[0]), "r"((a)[1]), "r"((a)[2]), "r"((a)[3]), "r"(b0), "r"(b1))

__device__ __forceinline__ unsigned pack2h(__half a, __half b) {
    return (unsigned)__half_as_ushort(a) | ((unsigned)__half_as_ushort(b) << 16);
}

// ---------------- Cayley: scale-free GJ inverse, register-blocked -----------
#define CLD 68
__global__ __launch_bounds__(32) void cayley_kernel(
    const float* __restrict__ Lin, const float* __restrict__ Rin) {
    __shared__ float C[64 * CLD];
    const int blk = blockIdx.x;
    const float* A = blk < 64 ? Lin + blk * 4096 : Rin + (blk - 64) * 4096;
    __half* Q = blk < 64 ? g_Lq + blk * 4096 : g_Rq + (blk - 64) * 4096;
    const int lane = threadIdx.x;
    const int r0 = lane, r1 = lane + 32;

    for (int e = lane; e < 4096; e += 32) {
        int i = e >> 6, j = e & 63;
        C[i * CLD + j] = ((i == j) ? 1.0f : 0.0f)
                       + 0.5f * (A[i * 64 + j] - A[j * 64 + i]);
    }
    __syncwarp();

    for (int k = 0; k < 64; k++) {
        float piv = __fdividef(1.0f, C[k * CLD + k]);
        float f0 = C[r0 * CLD + k] * piv;
        float f1 = C[r1 * CLD + k] * piv;
        bool u0 = (r0 != k), u1 = (r1 != k);
        __syncwarp();
        #pragma unroll
        for (int h = 0; h < 2; h++) {
            const float4* p4 = (const float4*)(C + k * CLD) + h * 8;
            float4* m0 = (float4*)(C + r0 * CLD) + h * 8;
            float4* m1 = (float4*)(C + r1 * CLD) + h * 8;
            float4 p[8], a[8], b[8];
            #pragma unroll
            for (int c = 0; c < 8; c++) p[c] = p4[c];
            #pragma unroll
            for (int c = 0; c < 8; c++) a[c] = m0[c];
            #pragma unroll
            for (int c = 0; c < 8; c++) b[c] = m1[c];
            #pragma unroll
            for (int c = 0; c < 8; c++) {
                a[c].x -= f0 * p[c].x; a[c].y -= f0 * p[c].y;
                a[c].z -= f0 * p[c].z; a[c].w -= f0 * p[c].w;
                b[c].x -= f1 * p[c].x; b[c].y -= f1 * p[c].y;
                b[c].z -= f1 * p[c].z; b[c].w -= f1 * p[c].w;
            }
            if (u0) {
                #pragma unroll
                for (int c = 0; c < 8; c++) m0[c] = a[c];
            }
            if (u1) {
                #pragma unroll
                for (int c = 0; c < 8; c++) m1[c] = b[c];
            }
        }
        if (u0) C[r0 * CLD + k] = -f0;
        else  { C[r0 * CLD + k] = 1.0f; C[r0 * CLD + 64] = piv; }
        if (u1) C[r1 * CLD + k] = -f1;
        else  { C[r1 * CLD + k] = 1.0f; C[r1 * CLD + 64] = piv; }
        __syncwarp();
    }

    for (int e = lane; e < 4096; e += 32) {
        int a = e >> 6, b = e & 63;
        float v = 2.0f * C[b * CLD + 64] * C[b * CLD + a] - (a == b ? 1.0f : 0.0f);
        Q[e] = __float2half_rn(v);
    }
}

// ---------------- Stage 1: 4 b-tiles/CTA, double-buffered A, hoisted B ------
#define S1_A0  0
#define S1_A1  16384
#define S1_BH  32768
#define S1_SMEM 40960
#define S1_TILES 4

__global__ __launch_bounds__(256, 2) void stage1_kernel(const float* __restrict__ x) {
    extern __shared__ char sm[];
    const unsigned sb = smem_u32(sm);
    const int tid = threadIdx.x, wid = tid >> 5, lane = tid & 31;
    const int rblk = blockIdx.x;
    const long bbase = (long)blockIdx.y * (128 * S1_TILES);

    const int wm = wid & 3, wn = wid >> 2;
    const int M0 = wm * 32, N0 = wn * 32;
    const int g = lane >> 2, t2 = (lane & 3) << 1;

    // B = Rq[rblk] -> smem (once)
    #pragma unroll
    for (int q = 0; q < 4; q++) {
        int f = q * 256 + tid;
        int row = f >> 4, c4 = f & 15;
        uint2 u = *(const uint2*)(g_Rq + (size_t)rblk * 4096 + f * 4);
        *(uint2*)(sm + S1_BH + SWZ((unsigned)(row * 128 + c4 * 8))) = u;
    }
    // x tile 0: LDG + convert to fp16 in registers
    uint2 xbuf[8];
    #pragma unroll
    for (int q = 0; q < 8; q++) {
        int f = q * 256 + tid;
        int row = f >> 4, p4 = f & 15;
        float4 v = *(const float4*)(x + (bbase + row) * 4096 + rblk * 64 + p4 * 4);
        xbuf[q] = make_uint2(pack2h(__float2half_rn(v.x), __float2half_rn(v.y)),
                             pack2h(__float2half_rn(v.z), __float2half_rn(v.w)));
    }
    // stage tile 0 into A0
    #pragma unroll
    for (int q = 0; q < 8; q++) {
        int f = q * 256 + tid;
        int row = f >> 4, p4 = f & 15;
        *(uint2*)(sm + S1_A0 + SWZ((unsigned)(row * 128 + p4 * 8))) = xbuf[q];
    }
    __syncthreads();

    // hoist B fragments (reused by all tiles)
    unsigned bfr[4][2][4];
    #pragma unroll
    for (int kk = 0; kk < 4; kk++)
        #pragma unroll
        for (int nh = 0; nh < 2; nh++) {
            unsigned row = N0 + nh * 16 + (lane & 7) + ((lane >> 4) << 3);
            unsigned ph = SWZ(row * 128 + kk * 32 + (((lane >> 3) & 1) << 4));
            LDSM4(bfr[kk][nh][0], bfr[kk][nh][1], bfr[kk][nh][2], bfr[kk][nh][3],
                  sb + S1_BH + ph);
        }

    for (int tb = 0; tb < S1_TILES; tb++) {
        const long b0 = bbase + tb * 128;
        const unsigned abase = sb + ((tb & 1) ? S1_A1 : S1_A0);
        if (tb > 0) {
            // stage prefetched tile into the other buffer, then one barrier
            #pragma unroll
            for (int q = 0; q < 8; q++) {
                int f = q * 256 + tid;
                int row = f >> 4, p4 = f & 15;
                *(uint2*)(sm + ((tb & 1) ? S1_A1 : S1_A0)
                          + SWZ((unsigned)(row * 128 + p4 * 8))) = xbuf[q];
            }
            __syncthreads();
        }
        // prefetch + convert next tile (overlaps LDSM/MMA/STG below)
        if (tb + 1 < S1_TILES) {
            #pragma unroll
            for (int q = 0; q < 8; q++) {
                int f = q * 256 + tid;
                int row = f >> 4, p4 = f & 15;
                float4 v = *(const float4*)(x + (b0 + 128 + row) * 4096
                                              + rblk * 64 + p4 * 4);
                xbuf[q] = make_uint2(
                    pack2h(__float2half_rn(v.x), __float2half_rn(v.y)),
                    pack2h(__float2half_rn(v.z), __float2half_rn(v.w)));
            }
        }

        float acc[2][4][4] = {};
        #pragma unroll
        for (int kk = 0; kk < 4; kk++) {
            unsigned ah[2][4];
            #pragma unroll
            for (int mt = 0; mt < 2; mt++) {
                unsigned row = M0 + mt * 16 + (lane & 15);
                unsigned ph = SWZ(row * 128 + kk * 32 + ((lane >> 4) << 4));
                LDSM4(ah[mt][0], ah[mt][1], ah[mt][2], ah[mt][3], abase + ph);
            }
            #pragma unroll
            for (int mt = 0; mt < 2; mt++)
                #pragma unroll
                for (int nh = 0; nh < 2; nh++) {
                    MMAF(acc[mt][nh * 2 + 0], ah[mt], bfr[kk][nh][0], bfr[kk][nh][1]);
                    MMAF(acc[mt][nh * 2 + 1], ah[mt], bfr[kk][nh][2], bfr[kk][nh][3]);
                }
        }

        // epilogue: fp16 STG to g_t[l][r][b]
        #pragma unroll
        for (int mt = 0; mt < 2; mt++) {
            const long bb = b0 + M0 + mt * 16 + g;
            #pragma unroll
            for (int nt = 0; nt < 4; nt++) {
                int l0 = N0 + nt * 8 + t2;
                size_t base = ((size_t)l0 * 64 + rblk) * 16384;
                g_t[base + bb]               = __float2half_rn(acc[mt][nt][0]);
                g_t[base + 1048576 + bb]     = __float2half_rn(acc[mt][nt][1]);
                g_t[base + bb + 8]           = __float2half_rn(acc[mt][nt][2]);
                g_t[base + 1048576 + bb + 8] = __float2half_rn(acc[mt][nt][3]);
            }
        }
    }
}

// ---------------- Stage 2: 2 b-tiles x 4 l's, hoisted W frags ----------------
// smem: At double buffer @0 (2 x 8KB); os 4 planes of 64x66 f32 @16384;
// W staging (32KB) OVERLAID on os (used only before first os write).
#define S2_AT0 0
#define S2_AT1 8192
#define S2_OS  16384
#define S2_W   16384
#define S2_SMEM (16384 + 4 * 4224 * 4)        // 83968
#define S2_TILES 2

__global__ __launch_bounds__(256, 2) void stage2_kernel(float* __restrict__ y) {
    extern __shared__ char sm[];
    const unsigned sb = smem_u32(sm);
    float* os = (float*)(sm + S2_OS);
    const int tid = threadIdx.x, wid = tid >> 5, lane = tid & 31;
    const int lg = blockIdx.x;                    // 0..15
    const long bbase = (long)blockIdx.y * (64 * S2_TILES);

    const int wm = wid & 1, wn = wid >> 1;        // warp tile m32 x n16
    const int M0 = wm * 32, N0 = wn * 16;
    const int g = lane >> 2, t2 = (lane & 3) << 1;

    // W planes -> smem (overlay region), once
    #pragma unroll
    for (int q = 0; q < 16; q++) {
        int f = q * 256 + tid;                    // 0..4095
        int pl = f >> 10, e = f & 1023;
        int r = e >> 4, b4 = e & 15;
        uint2 u = *(const uint2*)(g_Lq + (size_t)(lg * 4 + pl) * 4096 + e * 4);
        *(uint2*)(sm + S2_W + pl * 8192 + SWZ((unsigned)(r * 128 + b4 * 8))) = u;
    }
    // prefetch A (iter 0)
    uint2 abuf[4];
    #pragma unroll
    for (int q = 0; q < 4; q++) {
        int f = q * 256 + tid;
        int r = f >> 4, b4 = f & 15;
        abuf[q] = *(const uint2*)(g_t + ((size_t)(lg * 4) * 64 + r) * 16384
                                      + bbase + b4 * 4);
    }
    __syncthreads();

    // hoist ALL W fragments (4 planes x 4 kk), reused across both b-tiles
    unsigned wfr[4][4][4];
    #pragma unroll
    for (int ll = 0; ll < 4; ll++)
        #pragma unroll
        for (int kk = 0; kk < 4; kk++) {
            unsigned row = N0 + (lane & 7) + ((lane >> 4) << 3);
            unsigned ph = SWZ(row * 128 + kk * 32 + (((lane >> 3) & 1) << 4));
            LDSM4(wfr[ll][kk][0], wfr[ll][kk][1], wfr[ll][kk][2], wfr[ll][kk][3],
                  sb + S2_W + ll * 8192 + ph);
        }

    for (int tbi = 0; tbi < S2_TILES; tbi++) {
        const long b0 = bbase + tbi * 64;
        for (int ll = 0; ll < 4; ll++) {
            const int iter = tbi * 4 + ll;
            const unsigned atb = sb + ((iter & 1) ? S2_AT1 : S2_AT0);
            #pragma unroll
            for (int q = 0; q < 4; q++) {
                int f = q * 256 + tid;
                int r = f >> 4, b4 = f & 15;
                *(uint2*)(sm + ((iter & 1) ? S2_AT1 : S2_AT0)
                          + SWZ((unsigned)(r * 128 + b4 * 8))) = abuf[q];
            }
            __syncthreads();
            // prefetch next iteration's A
            if (iter + 1 < S2_TILES * 4) {
                int tn = (iter + 1) >> 2, ln = (iter + 1) & 3;
                const long bn = bbase + tn * 64;
                #pragma unroll
                for (int q = 0; q < 4; q++) {
                    int f = q * 256 + tid;
                    int r = f >> 4, b4 = f & 15;
                    abuf[q] = *(const uint2*)(g_t
                        + ((size_t)(lg * 4 + ln) * 64 + r) * 16384 + bn + b4 * 4);
                }
            }

            float acc[2][2][4] = {};
            #pragma unroll
            for (int kk = 0; kk < 4; kk++) {
                unsigned ah[2][4];
                #pragma unroll
                for (int mt = 0; mt < 2; mt++) {   // A via ldmatrix.trans
                    unsigned row = kk * 16 + (lane & 7) + ((lane >> 4) << 3);
                    unsigned cb = (M0 + mt * 16 + (((lane >> 3) & 1) << 3)) * 2;
                    unsigned ph = SWZ(row * 128 + cb);
                    LDSM4T(ah[mt][0], ah[mt][1], ah[mt][2], ah[mt][3], atb + ph);
                }
                #pragma unroll
                for (int mt = 0; mt < 2; mt++) {
                    MMAF(acc[mt][0], ah[mt], wfr[ll][kk][0], wfr[ll][kk][1]);
                    MMAF(acc[mt][1], ah[mt], wfr[ll][kk][2], wfr[ll][kk][3]);
                }
            }

            #pragma unroll
            for (int mt = 0; mt < 2; mt++)
                #pragma unroll
                for (int nt = 0; nt < 2; nt++) {
                    float* p = os + ll * 4224 + (M0 + mt * 16 + g) * 66
                                  + N0 + nt * 8 + t2;
                    *(float2*)p = make_float2(acc[mt][nt][0], acc[mt][nt][1]);
                    *(float2*)(p + 8 * 66) = make_float2(acc[mt][nt][2],
                                                         acc[mt][nt][3]);
                }
        }
        __syncthreads();   // all os planes visible

        // gather 4 l's per (b,s) -> one float4
        for (int e = tid; e < 4096; e += 256) {
            int b = e >> 6, s = e & 63;
            int idx = b * 66 + s;
            float4 v = make_float4(os[idx], os[4224 + idx],
                                   os[8448 + idx], os[12672 + idx]);
            *(float4*)(y + (b0 + b) * 4096 + s * 64 + lg * 4) = v;
        }
        // next tbi's first os write happens after that iteration's barrier,
        // which every warp reaches only after finishing this gather -> safe
    }
}

// ---------------------------------------------------------------------------
extern "C" void kernel_launch(void* const* d_in, const int* in_sizes, int n_in,
                              void* d_out, int out_size) {
    const float* x = (const float*)d_in[0];
    const float* L = (const float*)d_in[1];
    const float* R = (const float*)d_in[2];
    float* y = (float*)d_out;

    cudaFuncSetAttribute(stage1_kernel,
                         cudaFuncAttributeMaxDynamicSharedMemorySize, S1_SMEM);
    cudaFuncSetAttribute(stage2_kernel,
                         cudaFuncAttributeMaxDynamicSharedMemorySize, S2_SMEM);

    cayley_kernel<<<128, 32>>>(L, R);
    stage1_kernel<<<dim3(64, 32), 256, S1_SMEM>>>(x);
    stage2_kernel<<<dim3(16, 128), 256, S2_SMEM>>>(y);
}

// round 14
// speedup vs baseline: 4.5533x; 1.0044x over previous
#include <cuda_runtime.h>
#include <cuda_fp16.h>

// ---------------------------------------------------------------------------
// GSOrthogonal round 14: stage1 epilogue coalesced via smem [l][b] staging
// (was 64 scattered STG.16/thread -> 4-sector wavefronts). Stage2 + cayley
// identical to round 13. Math unchanged (pure fp16 operands, f32 acc).
//  stage1: g_t[l][r][b] = sum_p Rq[r][l][p] x[b][r*64+p]
//  stage2: y[b][s*64+l] = sum_r Lq[l][s][r] t[l][r][b]
// ---------------------------------------------------------------------------

__device__ __half g_Lq[64 * 64 * 64];
__device__ __half g_Rq[64 * 64 * 64];
__device__ __half g_t[(size_t)4096 * 16384];     // [l][r][b] fp16

__device__ __forceinline__ unsigned smem_u32(const void* p) {
    unsigned a;
    asm("{ .reg .u64 t; cvta.to.shared.u64 t, %1; cvt.u32.u64 %0, t; }"
        : "=r"(a) : "l"(p));
    return a;
}

#define SWZ(o) ((o) ^ (((o) >> 3) & 0x70u))

#define LDSM4(r0, r1, r2, r3, addr)                                           \
    asm volatile("ldmatrix.sync.aligned.m8n8.x4.shared.b16 {%0,%1,%2,%3},[%4];" \
        : "=r"(r0), "=r"(r1), "=r"(r2), "=r"(r3) : "r"(addr))
#define LDSM4T(r0, r1, r2, r3, addr)                                          \
    asm volatile("ldmatrix.sync.aligned.m8n8.x4.trans.shared.b16 {%0,%1,%2,%3},[%4];" \
        : "=r"(r0), "=r"(r1), "=r"(r2), "=r"(r3) : "r"(addr))
#define MMAF(d, a, b0, b1)                                                    \
    asm volatile("mma.sync.aligned.m16n8k16.row.col.f32.f16.f16.f32 "         \
        "{%0,%1,%2,%3},{%4,%5,%6,%7},{%8,%9},{%0,%1,%2,%3};"                  \
        : "+f"((d)[0]), "+f"((d)[1]), "+f"((d)[2]), "+f"((d)[3])              \
        : "r"((a)[0]), "r"((a)[1]), "r"((a)[2]), "r"((a)[3]), "r"(b0), "r"(b1))

__device__ __forceinline__ unsigned pack2h(__half a, __half b) {
    return (unsigned)__half_as_ushort(a) | ((unsigned)__half_as_ushort(b) << 16);
}

// ---------------- Cayley: scale-free GJ inverse, register-blocked -----------
#define CLD 68
__global__ __launch_bounds__(32) void cayley_kernel(
    const float* __restrict__ Lin, const float* __restrict__ Rin) {
    __shared__ float C[64 * CLD];
    const int blk = blockIdx.x;
    const float* A = blk < 64 ? Lin + blk * 4096 : Rin + (blk - 64) * 4096;
    __half* Q = blk < 64 ? g_Lq + blk * 4096 : g_Rq + (blk - 64) * 4096;
    const int lane = threadIdx.x;
    const int r0 = lane, r1 = lane + 32;

    for (int e = lane; e < 4096; e += 32) {
        int i = e >> 6, j = e & 63;
        C[i * CLD + j] = ((i == j) ? 1.0f : 0.0f)
                       + 0.5f * (A[i * 64 + j] - A[j * 64 + i]);
    }
    __syncwarp();

    for (int k = 0; k < 64; k++) {
        float piv = __fdividef(1.0f, C[k * CLD + k]);
        float f0 = C[r0 * CLD + k] * piv;
        float f1 = C[r1 * CLD + k] * piv;
        bool u0 = (r0 != k), u1 = (r1 != k);
        __syncwarp();
        #pragma unroll
        for (int h = 0; h < 2; h++) {
            const float4* p4 = (const float4*)(C + k * CLD) + h * 8;
            float4* m0 = (float4*)(C + r0 * CLD) + h * 8;
            float4* m1 = (float4*)(C + r1 * CLD) + h * 8;
            float4 p[8], a[8], b[8];
            #pragma unroll
            for (int c = 0; c < 8; c++) p[c] = p4[c];
            #pragma unroll
            for (int c = 0; c < 8; c++) a[c] = m0[c];
            #pragma unroll
            for (int c = 0; c < 8; c++) b[c] = m1[c];
            #pragma unroll
            for (int c = 0; c < 8; c++) {
                a[c].x -= f0 * p[c].x; a[c].y -= f0 * p[c].y;
                a[c].z -= f0 * p[c].z; a[c].w -= f0 * p[c].w;
                b[c].x -= f1 * p[c].x; b[c].y -= f1 * p[c].y;
                b[c].z -= f1 * p[c].z; b[c].w -= f1 * p[c].w;
            }
            if (u0) {
                #pragma unroll
                for (int c = 0; c < 8; c++) m0[c] = a[c];
            }
            if (u1) {
                #pragma unroll
                for (int c = 0; c < 8; c++) m1[c] = b[c];
            }
        }
        if (u0) C[r0 * CLD + k] = -f0;
        else  { C[r0 * CLD + k] = 1.0f; C[r0 * CLD + 64] = piv; }
        if (u1) C[r1 * CLD + k] = -f1;
        else  { C[r1 * CLD + k] = 1.0f; C[r1 * CLD + 64] = piv; }
        __syncwarp();
    }

    for (int e = lane; e < 4096; e += 32) {
        int a = e >> 6, b = e & 63;
        float v = 2.0f * C[b * CLD + 64] * C[b * CLD + a] - (a == b ? 1.0f : 0.0f);
        Q[e] = __float2half_rn(v);
    }
}

// ---------------- Stage 1: 4 b-tiles/CTA, coalesced epilogue ----------------
// smem: A 16KB @0; B 8KB @16384; os [64 l][136 halves] 17408B @24576
#define S1_A   0
#define S1_BH  16384
#define S1_OS  24576
#define S1_SMEM (24576 + 64 * 136 * 2)        // 41984
#define S1_TILES 4

__global__ __launch_bounds__(256, 2) void stage1_kernel(const float* __restrict__ x) {
    extern __shared__ char sm[];
    const unsigned sb = smem_u32(sm);
    __half* osp = (__half*)(sm + S1_OS);
    const int tid = threadIdx.x, wid = tid >> 5, lane = tid & 31;
    const int rblk = blockIdx.x;
    const long bbase = (long)blockIdx.y * (128 * S1_TILES);

    const int wm = wid & 3, wn = wid >> 2;
    const int M0 = wm * 32, N0 = wn * 32;
    const int g = lane >> 2, t2 = (lane & 3) << 1;

    // B = Rq[rblk] -> smem (once)
    #pragma unroll
    for (int q = 0; q < 4; q++) {
        int f = q * 256 + tid;
        int row = f >> 4, c4 = f & 15;
        uint2 u = *(const uint2*)(g_Rq + (size_t)rblk * 4096 + f * 4);
        *(uint2*)(sm + S1_BH + SWZ((unsigned)(row * 128 + c4 * 8))) = u;
    }
    // x tile 0: LDG + convert to fp16 in registers
    uint2 xbuf[8];
    #pragma unroll
    for (int q = 0; q < 8; q++) {
        int f = q * 256 + tid;
        int row = f >> 4, p4 = f & 15;
        float4 v = *(const float4*)(x + (bbase + row) * 4096 + rblk * 64 + p4 * 4);
        xbuf[q] = make_uint2(pack2h(__float2half_rn(v.x), __float2half_rn(v.y)),
                             pack2h(__float2half_rn(v.z), __float2half_rn(v.w)));
    }
    __syncthreads();   // B visible

    // hoist B fragments (reused by all tiles)
    unsigned bfr[4][2][4];
    #pragma unroll
    for (int kk = 0; kk < 4; kk++)
        #pragma unroll
        for (int nh = 0; nh < 2; nh++) {
            unsigned row = N0 + nh * 16 + (lane & 7) + ((lane >> 4) << 3);
            unsigned ph = SWZ(row * 128 + kk * 32 + (((lane >> 3) & 1) << 4));
            LDSM4(bfr[kk][nh][0], bfr[kk][nh][1], bfr[kk][nh][2], bfr[kk][nh][3],
                  sb + S1_BH + ph);
        }

    for (int tb = 0; tb < S1_TILES; tb++) {
        const long b0 = bbase + tb * 128;
        // stage registers -> A smem
        #pragma unroll
        for (int q = 0; q < 8; q++) {
            int f = q * 256 + tid;
            int row = f >> 4, p4 = f & 15;
            *(uint2*)(sm + S1_A + SWZ((unsigned)(row * 128 + p4 * 8))) = xbuf[q];
        }
        __syncthreads();   // A visible; prior tile's os gather also done
        // prefetch + convert next tile (overlaps LDSM/MMA below)
        if (tb + 1 < S1_TILES) {
            #pragma unroll
            for (int q = 0; q < 8; q++) {
                int f = q * 256 + tid;
                int row = f >> 4, p4 = f & 15;
                float4 v = *(const float4*)(x + (b0 + 128 + row) * 4096
                                              + rblk * 64 + p4 * 4);
                xbuf[q] = make_uint2(
                    pack2h(__float2half_rn(v.x), __float2half_rn(v.y)),
                    pack2h(__float2half_rn(v.z), __float2half_rn(v.w)));
            }
        }

        float acc[2][4][4] = {};
        #pragma unroll
        for (int kk = 0; kk < 4; kk++) {
            unsigned ah[2][4];
            #pragma unroll
            for (int mt = 0; mt < 2; mt++) {
                unsigned row = M0 + mt * 16 + (lane & 15);
                unsigned ph = SWZ(row * 128 + kk * 32 + ((lane >> 4) << 4));
                LDSM4(ah[mt][0], ah[mt][1], ah[mt][2], ah[mt][3], sb + S1_A + ph);
            }
            #pragma unroll
            for (int mt = 0; mt < 2; mt++)
                #pragma unroll
                for (int nh = 0; nh < 2; nh++) {
                    MMAF(acc[mt][nh * 2 + 0], ah[mt], bfr[kk][nh][0], bfr[kk][nh][1]);
                    MMAF(acc[mt][nh * 2 + 1], ah[mt], bfr[kk][nh][2], bfr[kk][nh][3]);
                }
        }

        // stage acc -> os[l][b] (halves, row pitch 136)
        #pragma unroll
        for (int mt = 0; mt < 2; mt++) {
            const int bb = M0 + mt * 16 + g;
            #pragma unroll
            for (int nt = 0; nt < 4; nt++) {
                int l0 = N0 + nt * 8 + t2;
                osp[l0 * 136 + bb]             = __float2half_rn(acc[mt][nt][0]);
                osp[(l0 + 1) * 136 + bb]       = __float2half_rn(acc[mt][nt][1]);
                osp[l0 * 136 + bb + 8]         = __float2half_rn(acc[mt][nt][2]);
                osp[(l0 + 1) * 136 + bb + 8]   = __float2half_rn(acc[mt][nt][3]);
            }
        }
        __syncthreads();   // os complete (also: all A reads done)

        // coalesced write: per warp one l-row chunk, 256B contiguous STG.64
        #pragma unroll
        for (int q = 0; q < 8; q++) {
            int e = q * 256 + tid;            // 0..2047 uint2 units
            int l = e >> 5, b4 = e & 31;
            uint2 v = *(const uint2*)((const char*)osp + l * 272 + b4 * 8);
            *(uint2*)(g_t + ((size_t)l * 64 + rblk) * 16384 + b0 + b4 * 4) = v;
        }
        // next tile's A STS is gated by the sync after it is written; os reuse
        // is gated by the sync following the next MMA block.
        __syncthreads();
    }
}

// ---------------- Stage 2: 2 b-tiles x 4 l's, hoisted W frags (= round 13) --
#define S2_AT0 0
#define S2_AT1 8192
#define S2_OS  16384
#define S2_W   16384
#define S2_SMEM (16384 + 4 * 4224 * 4)        // 83968
#define S2_TILES 2

__global__ __launch_bounds__(256, 2) void stage2_kernel(float* __restrict__ y) {
    extern __shared__ char sm[];
    const unsigned sb = smem_u32(sm);
    float* os = (float*)(sm + S2_OS);
    const int tid = threadIdx.x, wid = tid >> 5, lane = tid & 31;
    const int lg = blockIdx.x;                    // 0..15
    const long bbase = (long)blockIdx.y * (64 * S2_TILES);

    const int wm = wid & 1, wn = wid >> 1;        // warp tile m32 x n16
    const int M0 = wm * 32, N0 = wn * 16;
    const int g = lane >> 2, t2 = (lane & 3) << 1;

    // W planes -> smem (overlay region), once
    #pragma unroll
    for (int q = 0; q < 16; q++) {
        int f = q * 256 + tid;                    // 0..4095
        int pl = f >> 10, e = f & 1023;
        int r = e >> 4, b4 = e & 15;
        uint2 u = *(const uint2*)(g_Lq + (size_t)(lg * 4 + pl) * 4096 + e * 4);
        *(uint2*)(sm + S2_W + pl * 8192 + SWZ((unsigned)(r * 128 + b4 * 8))) = u;
    }
    // prefetch A (iter 0)
    uint2 abuf[4];
    #pragma unroll
    for (int q = 0; q < 4; q++) {
        int f = q * 256 + tid;
        int r = f >> 4, b4 = f & 15;
        abuf[q] = *(const uint2*)(g_t + ((size_t)(lg * 4) * 64 + r) * 16384
                                      + bbase + b4 * 4);
    }
    __syncthreads();

    // hoist ALL W fragments (4 planes x 4 kk), reused across both b-tiles
    unsigned wfr[4][4][4];
    #pragma unroll
    for (int ll = 0; ll < 4; ll++)
        #pragma unroll
        for (int kk = 0; kk < 4; kk++) {
            unsigned row = N0 + (lane & 7) + ((lane >> 4) << 3);
            unsigned ph = SWZ(row * 128 + kk * 32 + (((lane >> 3) & 1) << 4));
            LDSM4(wfr[ll][kk][0], wfr[ll][kk][1], wfr[ll][kk][2], wfr[ll][kk][3],
                  sb + S2_W + ll * 8192 + ph);
        }

    for (int tbi = 0; tbi < S2_TILES; tbi++) {
        const long b0 = bbase + tbi * 64;
        for (int ll = 0; ll < 4; ll++) {
            const int iter = tbi * 4 + ll;
            const unsigned atb = sb + ((iter & 1) ? S2_AT1 : S2_AT0);
            #pragma unroll
            for (int q = 0; q < 4; q++) {
                int f = q * 256 + tid;
                int r = f >> 4, b4 = f & 15;
                *(uint2*)(sm + ((iter & 1) ? S2_AT1 : S2_AT0)
                          + SWZ((unsigned)(r * 128 + b4 * 8))) = abuf[q];
            }
            __syncthreads();
            if (iter + 1 < S2_TILES * 4) {
                int tn = (iter + 1) >> 2, ln = (iter + 1) & 3;
                const long bn = bbase + tn * 64;
                #pragma unroll
                for (int q = 0; q < 4; q++) {
                    int f = q * 256 + tid;
                    int r = f >> 4, b4 = f & 15;
                    abuf[q] = *(const uint2*)(g_t
                        + ((size_t)(lg * 4 + ln) * 64 + r) * 16384 + bn + b4 * 4);
                }
            }

            float acc[2][2][4] = {};
            #pragma unroll
            for (int kk = 0; kk < 4; kk++) {
                unsigned ah[2][4];
                #pragma unroll
                for (int mt = 0; mt < 2; mt++) {   // A via ldmatrix.trans
                    unsigned row = kk * 16 + (lane & 7) + ((lane >> 4) << 3);
                    unsigned cb = (M0 + mt * 16 + (((lane >> 3) & 1) << 3)) * 2;
                    unsigned ph = SWZ(row * 128 + cb);
                    LDSM4T(ah[mt][0], ah[mt][1], ah[mt][2], ah[mt][3], atb + ph);
                }
                #pragma unroll
                for (int mt = 0; mt < 2; mt++) {
                    MMAF(acc[mt][0], ah[mt], wfr[ll][kk][0], wfr[ll][kk][1]);
                    MMAF(acc[mt][1], ah[mt], wfr[ll][kk][2], wfr[ll][kk][3]);
                }
            }

            #pragma unroll
            for (int mt = 0; mt < 2; mt++)
                #pragma unroll
                for (int nt = 0; nt < 2; nt++) {
                    float* p = os + ll * 4224 + (M0 + mt * 16 + g) * 66
                                  + N0 + nt * 8 + t2;
                    *(float2*)p = make_float2(acc[mt][nt][0], acc[mt][nt][1]);
                    *(float2*)(p + 8 * 66) = make_float2(acc[mt][nt][2],
                                                         acc[mt][nt][3]);
                }
        }
        __syncthreads();   // all os planes visible

        for (int e = tid; e < 4096; e += 256) {
            int b = e >> 6, s = e & 63;
            int idx = b * 66 + s;
            float4 v = make_float4(os[idx], os[4224 + idx],
                                   os[8448 + idx], os[12672 + idx]);
            *(float4*)(y + (b0 + b) * 4096 + s * 64 + lg * 4) = v;
        }
    }
}

// ---------------------------------------------------------------------------
extern "C" void kernel_launch(void* const* d_in, const int* in_sizes, int n_in,
                              void* d_out, int out_size) {
    const float* x = (const float*)d_in[0];
    const float* L = (const float*)d_in[1];
    const float* R = (const float*)d_in[2];
    float* y = (float*)d_out;

    cudaFuncSetAttribute(stage1_kernel,
                         cudaFuncAttributeMaxDynamicSharedMemorySize, S1_SMEM);
    cudaFuncSetAttribute(stage2_kernel,
                         cudaFuncAttributeMaxDynamicSharedMemorySize, S2_SMEM);

    cayley_kernel<<<128, 32>>>(L, R);
    stage1_kernel<<<dim3(64, 32), 256, S1_SMEM>>>(x);
    stage2_kernel<<<dim3(16, 128), 256, S2_SMEM>>>(y);
}